// round 9
// baseline (speedup 1.0000x reference)
#include <cuda_runtime.h>
#include <cuda_bf16.h>
#include <float.h>
#include <math.h>

// ---------------- problem constants ----------------
#define NL   12
#define D    768
#define NH   12
#define HD   64
#define VV   50257
#define BB   4
#define TT   1024
#define BT   (BB*TT)          // 4096
#define FF   (4*D)            // 3072
#define BH   (BB*NH)          // 48
#define EPSF 1e-5f
#define SCALE 0.125f          // HD^-0.5

// ---------------- scratch (device globals; no runtime alloc) ----------------
__device__ float g_x[BT*D];
__device__ float g_h[BT*D];
__device__ float g_q[BT*D];
__device__ float g_k[BT*D];
__device__ float g_v[BT*D];
__device__ float g_o[BT*D];
__device__ float g_ff[BT*FF];
__device__ float g_att[(size_t)BH*TT*TT];   // 201 MB
__device__ float g_nll[BT];

// ---------------- tf32 / async helpers ----------------
__device__ __forceinline__ unsigned f2tf(float x) {
    unsigned r;
    asm("cvt.rna.tf32.f32 %0, %1;" : "=r"(r) : "f"(x));
    return r;
}
__device__ __forceinline__ float tf32f(float x) { return __uint_as_float(f2tf(x)); }

__device__ __forceinline__ void mma_tf32(float* d, const unsigned* a, const unsigned* b) {
    asm volatile(
        "mma.sync.aligned.m16n8k8.row.col.f32.tf32.tf32.f32 "
        "{%0,%1,%2,%3}, {%4,%5,%6,%7}, {%8,%9}, {%0,%1,%2,%3};"
        : "+f"(d[0]), "+f"(d[1]), "+f"(d[2]), "+f"(d[3])
        : "r"(a[0]), "r"(a[1]), "r"(a[2]), "r"(a[3]), "r"(b[0]), "r"(b[1]));
}
__device__ __forceinline__ void cp16(void* s, const void* g) {
    unsigned sa = (unsigned)__cvta_generic_to_shared(s);
    asm volatile("cp.async.cg.shared.global [%0], [%1], 16;" :: "r"(sa), "l"(g));
}
__device__ __forceinline__ void cp4z(void* s, const void* g, int srcbytes) {
    unsigned sa = (unsigned)__cvta_generic_to_shared(s);
    asm volatile("cp.async.ca.shared.global [%0], [%1], 4, %2;"
                 :: "r"(sa), "l"(g), "r"(srcbytes));
}
#define CP_COMMIT() asm volatile("cp.async.commit_group;")
#define CP_WAIT1()  asm volatile("cp.async.wait_group 1;")

// ---------------- tf32 rounding pass ----------------
__global__ void round_kernel(const float* __restrict__ in, float* __restrict__ out,
                             long long n) {
    long long i = (long long)blockIdx.x * blockDim.x + threadIdx.x;
    long long stride = (long long)gridDim.x * blockDim.x;
    for (; i < n; i += stride) out[i] = tf32f(in[i]);
}

// ---------------- embedding ----------------
__global__ void embed_kernel(const int* __restrict__ idx,
                             const float* __restrict__ tok,
                             const float* __restrict__ pos,
                             float* __restrict__ x) {
    int i = blockIdx.x * 256 + threadIdx.x;
    if (i >= BT * D) return;
    int row = i / D;
    int d   = i - row * D;
    int t   = row & (TT - 1);
    x[i] = tok[(size_t)idx[row] * D + d] + pos[(size_t)t * D + d];
}

// ---------------- layernorm (output pre-rounded to tf32) ----------------
__global__ void ln_kernel(const float* __restrict__ x,
                          const float* __restrict__ g,
                          const float* __restrict__ b,
                          float* __restrict__ out) {
    int row = blockIdx.x;
    const float* xr = x + (size_t)row * D;
    __shared__ float sx[D];
    __shared__ float red[256];
    int tid = threadIdx.x;

    float s = 0.f;
    for (int i = tid; i < D; i += 256) { float t = xr[i]; sx[i] = t; s += t; }
    red[tid] = s; __syncthreads();
    #pragma unroll
    for (int off = 128; off > 0; off >>= 1) {
        if (tid < off) red[tid] += red[tid + off];
        __syncthreads();
    }
    float mean = red[0] * (1.f / D);
    __syncthreads();

    float s2 = 0.f;
    for (int i = tid; i < D; i += 256) { float t = sx[i] - mean; s2 += t * t; }
    red[tid] = s2; __syncthreads();
    #pragma unroll
    for (int off = 128; off > 0; off >>= 1) {
        if (tid < off) red[tid] += red[tid + off];
        __syncthreads();
    }
    float rstd = rsqrtf(red[0] * (1.f / D) + EPSF);

    float* orow = out + (size_t)row * D;
    for (int i = tid; i < D; i += 256)
        orow[i] = tf32f((sx[i] - mean) * rstd * g[i] + b[i]);
}

// ---------------- TF32 GEMM, 128x64x32 block (R6 core; FF1 + LM head) ----------------
#define AK    36
#define BN2   68
#define ASTG  (128*AK)          // 4608
#define BSTG  (32*BN2)          // 2176
#define BOFF  (2*ASTG)
#define GSMEM ((2*ASTG + 2*BSTG) * 4)   // 54272 bytes

__global__ __launch_bounds__(128, 3)
void gemm_tf32(const float* __restrict__ A, const float* __restrict__ Bm,
               const float* __restrict__ bias, const float* __restrict__ resid,
               float* __restrict__ C, int M, int Ncols, int K, int ldB, int ldC,
               int relu, int roundC) {
    extern __shared__ float smem[];

    const int tid  = threadIdx.x;
    const int lane = tid & 31;
    const int wid  = tid >> 5;
    const int warpM = (wid >> 1) * 64;
    const int warpN = (wid & 1) * 32;
    const int gm = blockIdx.x * 128;
    const int gn = blockIdx.y * 64;
    const int lt = lane & 3;
    const int lg = lane >> 2;
    const bool alignedB = ((ldB & 3) == 0) && (gn + 64 <= ldB);

    float acc[4][4][4];
    #pragma unroll
    for (int mi = 0; mi < 4; mi++)
        #pragma unroll
        for (int nj = 0; nj < 4; nj++)
            #pragma unroll
            for (int r = 0; r < 4; r++) acc[mi][nj][r] = 0.f;

    const int nch = K >> 5;

    auto load_tiles = [&](int k0, int stage) {
        float* As = smem + stage * ASTG;
        float* Bs = smem + BOFF + stage * BSTG;
        #pragma unroll
        for (int i = 0; i < 8; i++) {
            int c  = tid + i * 128;        // 0..1023
            int m  = c >> 3;
            int k4 = (c & 7) << 2;
            cp16(As + m * AK + k4, A + (size_t)(gm + m) * K + k0 + k4);
        }
        if (alignedB) {
            #pragma unroll
            for (int i = 0; i < 4; i++) {
                int c  = tid + i * 128;    // 0..511
                int kr = c >> 4;
                int n4 = (c & 15) << 2;
                cp16(Bs + kr * BN2 + n4, Bm + (size_t)(k0 + kr) * ldB + gn + n4);
            }
        } else {
            #pragma unroll
            for (int i = 0; i < 16; i++) {
                int c  = tid + i * 128;    // 0..2047
                int kr = c >> 6;
                int n  = c & 63;
                int col = gn + n;
                cp4z(Bs + kr * BN2 + n, Bm + (size_t)(k0 + kr) * ldB + col,
                     (col < ldB) ? 4 : 0);
            }
        }
    };

    load_tiles(0, 0);
    CP_COMMIT();

    unsigned a[2][4][4], b[2][4][2];

    for (int ch = 0; ch < nch; ch++) {
        int stage = ch & 1;
        if (ch + 1 < nch) load_tiles((ch + 1) << 5, stage ^ 1);
        CP_COMMIT();
        CP_WAIT1();
        __syncthreads();

        const float* Asb = smem + stage * ASTG;
        const float* Bsb = smem + BOFF + stage * BSTG;

        auto load_frag = [&](int kk, int buf) {
            #pragma unroll
            for (int mi = 0; mi < 4; mi++) {
                const float* p0 = Asb + (warpM + mi * 16 + lg) * AK + kk;
                const float* p1 = p0 + 8 * AK;
                a[buf][mi][0] = __float_as_uint(p0[lt]);
                a[buf][mi][1] = __float_as_uint(p1[lt]);
                a[buf][mi][2] = __float_as_uint(p0[lt + 4]);
                a[buf][mi][3] = __float_as_uint(p1[lt + 4]);
            }
            #pragma unroll
            for (int nj = 0; nj < 4; nj++) {
                int nc = warpN + nj * 8 + lg;
                b[buf][nj][0] = f2tf(Bsb[(kk + lt) * BN2 + nc]);
                b[buf][nj][1] = f2tf(Bsb[(kk + lt + 4) * BN2 + nc]);
            }
        };

        load_frag(0, 0);
        #pragma unroll
        for (int kks = 0; kks < 4; kks++) {
            int cur = kks & 1;
            if (kks < 3) load_frag((kks + 1) << 3, cur ^ 1);
            #pragma unroll
            for (int mi = 0; mi < 4; mi++)
                #pragma unroll
                for (int nj = 0; nj < 4; nj++)
                    mma_tf32(acc[mi][nj], a[cur][mi], b[cur][nj]);
        }
        __syncthreads();
    }

    #pragma unroll
    for (int mi = 0; mi < 4; mi++) {
        int r0 = gm + warpM + mi * 16 + lg;
        #pragma unroll
        for (int nj = 0; nj < 4; nj++) {
            int c0 = gn + warpN + nj * 8 + (lt << 1);
            #pragma unroll
            for (int r = 0; r < 4; r++) {
                int rowg = r0 + ((r >> 1) << 3);
                int colg = c0 + (r & 1);
                if (colg < Ncols) {
                    float v = acc[mi][nj][r];
                    if (bias)   v += bias[colg];
                    if (resid)  v += resid[(size_t)rowg * ldC + colg];
                    if (relu)   v = fmaxf(v, 0.f);
                    if (roundC) v = tf32f(v);
                    C[(size_t)rowg * ldC + colg] = v;
                }
            }
        }
    }
}

// ---------------- TF32 GEMM, 64x64x32 block (N=768 GEMMs: Q,K,V,Wo,FF2) ----------------
// 128 threads = 4 warps as 2(M)x2(N), warp tile 32x32. Requires M%64==0, N%64==0, K%32==0.
#define A64STG (64*AK)           // 2304
#define B64OFF (2*A64STG)
#define GSMEM64 ((2*A64STG + 2*BSTG) * 4)   // 35840 bytes

__global__ __launch_bounds__(128, 4)
void gemm64(const float* __restrict__ A, const float* __restrict__ Bm,
            const float* __restrict__ bias, const float* __restrict__ resid,
            float* __restrict__ C, int M, int N, int K, int relu, int roundC) {
    extern __shared__ float smem[];

    const int tid  = threadIdx.x;
    const int lane = tid & 31;
    const int wid  = tid >> 5;
    const int warpM = (wid >> 1) * 32;
    const int warpN = (wid & 1) * 32;
    const int gm = blockIdx.x * 64;
    const int gn = blockIdx.y * 64;
    const int lt = lane & 3;
    const int lg = lane >> 2;

    float acc[2][4][4];
    #pragma unroll
    for (int mi = 0; mi < 2; mi++)
        #pragma unroll
        for (int nj = 0; nj < 4; nj++)
            #pragma unroll
            for (int r = 0; r < 4; r++) acc[mi][nj][r] = 0.f;

    const int nch = K >> 5;

    auto load_tiles = [&](int k0, int stage) {
        float* As = smem + stage * A64STG;
        float* Bs = smem + B64OFF + stage * BSTG;
        #pragma unroll
        for (int i = 0; i < 4; i++) {
            int c  = tid + i * 128;        // 0..511 : A 64x32
            int m  = c >> 3;
            int k4 = (c & 7) << 2;
            cp16(As + m * AK + k4, A + (size_t)(gm + m) * K + k0 + k4);
        }
        #pragma unroll
        for (int i = 0; i < 4; i++) {
            int c  = tid + i * 128;        // 0..511 : B 32x64
            int kr = c >> 4;
            int n4 = (c & 15) << 2;
            cp16(Bs + kr * BN2 + n4, Bm + (size_t)(k0 + kr) * N + gn + n4);
        }
    };

    load_tiles(0, 0);
    CP_COMMIT();

    for (int ch = 0; ch < nch; ch++) {
        int stage = ch & 1;
        if (ch + 1 < nch) load_tiles((ch + 1) << 5, stage ^ 1);
        CP_COMMIT();
        CP_WAIT1();
        __syncthreads();

        const float* Asb = smem + stage * A64STG;
        const float* Bsb = smem + B64OFF + stage * BSTG;

        #pragma unroll
        for (int kk = 0; kk < 32; kk += 8) {
            unsigned a[2][4], b[4][2];
            #pragma unroll
            for (int mi = 0; mi < 2; mi++) {
                const float* p0 = Asb + (warpM + mi * 16 + lg) * AK + kk;
                const float* p1 = p0 + 8 * AK;
                a[mi][0] = __float_as_uint(p0[lt]);
                a[mi][1] = __float_as_uint(p1[lt]);
                a[mi][2] = __float_as_uint(p0[lt + 4]);
                a[mi][3] = __float_as_uint(p1[lt + 4]);
            }
            #pragma unroll
            for (int nj = 0; nj < 4; nj++) {
                int nc = warpN + nj * 8 + lg;
                b[nj][0] = f2tf(Bsb[(kk + lt) * BN2 + nc]);
                b[nj][1] = f2tf(Bsb[(kk + lt + 4) * BN2 + nc]);
            }
            #pragma unroll
            for (int mi = 0; mi < 2; mi++)
                #pragma unroll
                for (int nj = 0; nj < 4; nj++)
                    mma_tf32(acc[mi][nj], a[mi], b[nj]);
        }
        __syncthreads();
    }

    #pragma unroll
    for (int mi = 0; mi < 2; mi++) {
        int r0 = gm + warpM + mi * 16 + lg;
        #pragma unroll
        for (int nj = 0; nj < 4; nj++) {
            int c0 = gn + warpN + nj * 8 + (lt << 1);
            #pragma unroll
            for (int r = 0; r < 4; r++) {
                int rowg = r0 + ((r >> 1) << 3);
                int colg = c0 + (r & 1);
                float v = acc[mi][nj][r];
                if (bias)   v += bias[colg];
                if (resid)  v += resid[(size_t)rowg * N + colg];
                if (relu)   v = fmaxf(v, 0.f);
                if (roundC) v = tf32f(v);
                C[(size_t)rowg * N + colg] = v;
            }
        }
    }
}

// ---------------- attention scores via tf32 mma: scale * Q K^T + causal ----------------
#define QP 68
#define KP 65
__global__ __launch_bounds__(128)
void attn_scores(const float* __restrict__ q, const float* __restrict__ k,
                 float* __restrict__ att) {
    int tb = blockIdx.x, sb = blockIdx.y, bh = blockIdx.z;
    if (sb > tb) return;
    int b = bh / NH, h = bh % NH;

    __shared__ float Qs[64 * QP];   // [m][d]
    __shared__ float Ks[64 * KP];   // [d][s]
    const int tid  = threadIdx.x;
    const int lane = tid & 31;
    const int wid  = tid >> 5;
    const int warpM = (wid >> 1) * 32;
    const int warpN = (wid & 1) * 32;
    const int lt = lane & 3;
    const int lg = lane >> 2;

    const float* qb = q + (size_t)b * TT * D + (size_t)h * HD;
    const float* kb = k + (size_t)b * TT * D + (size_t)h * HD;

    #pragma unroll
    for (int i = 0; i < 8; i++) {
        int c  = tid + i * 128;
        int m  = c >> 4;
        int d4 = (c & 15) << 2;
        *(float4*)(Qs + m * QP + d4) =
            *(const float4*)(qb + (size_t)(tb * 64 + m) * D + d4);
    }
    #pragma unroll
    for (int i = 0; i < 32; i++) {
        int c = tid + i * 128;
        int s = c >> 6;
        int d = c & 63;
        Ks[d * KP + s] = kb[(size_t)(sb * 64 + s) * D + d];
    }
    __syncthreads();

    float acc[2][4][4];
    #pragma unroll
    for (int mi = 0; mi < 2; mi++)
        #pragma unroll
        for (int nj = 0; nj < 4; nj++)
            #pragma unroll
            for (int r = 0; r < 4; r++) acc[mi][nj][r] = 0.f;

    #pragma unroll
    for (int kk = 0; kk < 64; kk += 8) {
        unsigned a[2][4], bfr[4][2];
        #pragma unroll
        for (int mi = 0; mi < 2; mi++) {
            const float* p0 = Qs + (warpM + mi * 16 + lg) * QP + kk;
            const float* p1 = p0 + 8 * QP;
            a[mi][0] = f2tf(p0[lt]);
            a[mi][1] = f2tf(p1[lt]);
            a[mi][2] = f2tf(p0[lt + 4]);
            a[mi][3] = f2tf(p1[lt + 4]);
        }
        #pragma unroll
        for (int nj = 0; nj < 4; nj++) {
            int nc = warpN + nj * 8 + lg;
            bfr[nj][0] = f2tf(Ks[(kk + lt) * KP + nc]);
            bfr[nj][1] = f2tf(Ks[(kk + lt + 4) * KP + nc]);
        }
        #pragma unroll
        for (int mi = 0; mi < 2; mi++)
            #pragma unroll
            for (int nj = 0; nj < 4; nj++)
                mma_tf32(acc[mi][nj], a[mi], bfr[nj]);
    }

    float* out = att + ((size_t)bh * TT + (size_t)tb * 64) * TT + (size_t)sb * 64;
    #pragma unroll
    for (int mi = 0; mi < 2; mi++) {
        int tl0 = warpM + mi * 16 + lg;
        #pragma unroll
        for (int nj = 0; nj < 4; nj++) {
            int sl0 = warpN + nj * 8 + (lt << 1);
            #pragma unroll
            for (int r = 0; r < 4; r++) {
                int tl = tl0 + ((r >> 1) << 3);
                int sl = sl0 + (r & 1);
                int tg = tb * 64 + tl;
                int sg = sb * 64 + sl;
                out[(size_t)tl * TT + sl] =
                    (sg <= tg) ? acc[mi][nj][r] * SCALE : -3.402823466e38f;
            }
        }
    }
}

// ---------------- attention row softmax (fast exp) ----------------
__global__ void attn_softmax(float* __restrict__ att) {
    int row = blockIdx.x;
    int t = row & (TT - 1);
    float* p = att + (size_t)row * TT;
    int L = ((t >> 6) + 1) << 6;
    int tid = threadIdx.x;

    float m = -FLT_MAX;
    for (int i = tid; i < L; i += 256) m = fmaxf(m, p[i]);
    __shared__ float sm[256], ss[256];
    sm[tid] = m; __syncthreads();
    #pragma unroll
    for (int off = 128; off > 0; off >>= 1) {
        if (tid < off) sm[tid] = fmaxf(sm[tid], sm[tid + off]);
        __syncthreads();
    }
    float gm = sm[0];

    float s = 0.f;
    for (int i = tid; i < L; i += 256) s += __expf(p[i] - gm);
    ss[tid] = s; __syncthreads();
    #pragma unroll
    for (int off = 128; off > 0; off >>= 1) {
        if (tid < off) ss[tid] += ss[tid + off];
        __syncthreads();
    }
    float inv = 1.f / ss[0];
    for (int i = tid; i < L; i += 256)
        p[i] = __expf(p[i] - gm) * inv;
}

// ---------------- attention PV via tf32 mma: O = P @ V ----------------
#define PP 68
#define VP 68
__global__ __launch_bounds__(128)
void attn_pv(const float* __restrict__ att, const float* __restrict__ v,
             float* __restrict__ o) {
    int tb = blockIdx.x, bh = blockIdx.y;
    int b = bh / NH, h = bh % NH;

    __shared__ float Ps[64 * PP];   // [t][s]
    __shared__ float Vs[64 * VP];   // [s][d]
    const int tid  = threadIdx.x;
    const int lane = tid & 31;
    const int wid  = tid >> 5;
    const int warpM = (wid >> 1) * 32;
    const int warpN = (wid & 1) * 32;
    const int lt = lane & 3;
    const int lg = lane >> 2;

    const float* arow = att + ((size_t)bh * TT + (size_t)tb * 64) * TT;
    const float* vb = v + (size_t)b * TT * D + (size_t)h * HD;
    int Smax = (tb + 1) * 64;

    float acc[2][4][4];
    #pragma unroll
    for (int mi = 0; mi < 2; mi++)
        #pragma unroll
        for (int nj = 0; nj < 4; nj++)
            #pragma unroll
            for (int r = 0; r < 4; r++) acc[mi][nj][r] = 0.f;

    for (int s0 = 0; s0 < Smax; s0 += 64) {
        #pragma unroll
        for (int i = 0; i < 8; i++) {
            int c  = tid + i * 128;
            int m  = c >> 4;
            int s4 = (c & 15) << 2;
            *(float4*)(Ps + m * PP + s4) =
                *(const float4*)(arow + (size_t)m * TT + s0 + s4);
            *(float4*)(Vs + m * VP + s4) =
                *(const float4*)(vb + (size_t)(s0 + m) * D + s4);
        }
        __syncthreads();

        #pragma unroll
        for (int kk = 0; kk < 64; kk += 8) {
            unsigned a[2][4], bfr[4][2];
            #pragma unroll
            for (int mi = 0; mi < 2; mi++) {
                const float* p0 = Ps + (warpM + mi * 16 + lg) * PP + kk;
                const float* p1 = p0 + 8 * PP;
                a[mi][0] = f2tf(p0[lt]);
                a[mi][1] = f2tf(p1[lt]);
                a[mi][2] = f2tf(p0[lt + 4]);
                a[mi][3] = f2tf(p1[lt + 4]);
            }
            #pragma unroll
            for (int nj = 0; nj < 4; nj++) {
                int nc = warpN + nj * 8 + lg;
                bfr[nj][0] = f2tf(Vs[(kk + lt) * VP + nc]);
                bfr[nj][1] = f2tf(Vs[(kk + lt + 4) * VP + nc]);
            }
            #pragma unroll
            for (int mi = 0; mi < 2; mi++)
                #pragma unroll
                for (int nj = 0; nj < 4; nj++)
                    mma_tf32(acc[mi][nj], a[mi], bfr[nj]);
        }
        __syncthreads();
    }

    float* ob = o + (size_t)(b * TT + tb * 64) * D + (size_t)h * HD;
    #pragma unroll
    for (int mi = 0; mi < 2; mi++) {
        int tl0 = warpM + mi * 16 + lg;
        #pragma unroll
        for (int nj = 0; nj < 4; nj++) {
            int dl0 = warpN + nj * 8 + (lt << 1);
            #pragma unroll
            for (int r = 0; r < 4; r++) {
                int tl = tl0 + ((r >> 1) << 3);
                int dl = dl0 + (r & 1);
                ob[(size_t)tl * D + dl] = tf32f(acc[mi][nj][r]);
            }
        }
    }
}

// ---------------- per-row NLL over vocab ----------------
__global__ void nll_kernel(const float* __restrict__ logits,
                           const int* __restrict__ targets,
                           float* __restrict__ nll) {
    int row = blockIdx.x;
    const float* lr = logits + (size_t)row * VV;
    int tid = threadIdx.x;
    __shared__ float red[256];

    float m = -FLT_MAX;
    for (int i = tid; i < VV; i += 256) m = fmaxf(m, lr[i]);
    red[tid] = m; __syncthreads();
    #pragma unroll
    for (int off = 128; off > 0; off >>= 1) {
        if (tid < off) red[tid] = fmaxf(red[tid], red[tid + off]);
        __syncthreads();
    }
    float gm = red[0];
    __syncthreads();

    float s0 = 0.f, s1 = 0.f, s2 = 0.f, s3 = 0.f;
    int i = tid;
    for (; i + 768 < VV; i += 1024) {
        s0 += __expf(lr[i]       - gm);
        s1 += __expf(lr[i + 256] - gm);
        s2 += __expf(lr[i + 512] - gm);
        s3 += __expf(lr[i + 768] - gm);
    }
    for (; i < VV; i += 256) s0 += __expf(lr[i] - gm);
    red[tid] = (s0 + s1) + (s2 + s3); __syncthreads();
    #pragma unroll
    for (int off = 128; off > 0; off >>= 1) {
        if (tid < off) red[tid] += red[tid + off];
        __syncthreads();
    }
    if (tid == 0)
        nll[row] = gm + logf(red[0]) - lr[targets[row]];
}

__global__ void loss_kernel(const float* __restrict__ nll, float* __restrict__ dst,
                            int nextra) {
    __shared__ float red[256];
    int tid = threadIdx.x;
    float s = 0.f;
    for (int i = tid; i < BT; i += 256) s += nll[i];
    red[tid] = s; __syncthreads();
    #pragma unroll
    for (int off = 128; off > 0; off >>= 1) {
        if (tid < off) red[tid] += red[tid + off];
        __syncthreads();
    }
    if (tid == 0) {
        float loss = red[0] * (1.f / BT);
        for (int i = 0; i < nextra; i++) dst[i] = loss;
    }
}

// ---------------- launch ----------------
extern "C" void kernel_launch(void* const* d_in, const int* in_sizes, int n_in,
                              void* d_out, int out_size) {
    const int*   idx     = (const int*)  d_in[0];
    const int*   targets = (const int*)  d_in[1];
    const float* tok_emb = (const float*)d_in[2];
    const float* pos_emb = (const float*)d_in[3];
    const float* Wq      = (const float*)d_in[4];
    const float* Wk      = (const float*)d_in[5];
    const float* Wv      = (const float*)d_in[6];
    const float* Wo      = (const float*)d_in[7];
    const float* bo      = (const float*)d_in[8];
    const float* ln1_g   = (const float*)d_in[9];
    const float* ln1_b   = (const float*)d_in[10];
    const float* ln2_g   = (const float*)d_in[11];
    const float* ln2_b   = (const float*)d_in[12];
    const float* W1      = (const float*)d_in[13];
    const float* b1      = (const float*)d_in[14];
    const float* W2      = (const float*)d_in[15];
    const float* b2      = (const float*)d_in[16];
    const float* Wlm     = (const float*)d_in[17];
    const float* blm     = (const float*)d_in[18];

    float *x, *h, *q, *k, *v, *o, *ff, *att, *nll;
    cudaGetSymbolAddress((void**)&x,   g_x);
    cudaGetSymbolAddress((void**)&h,   g_h);
    cudaGetSymbolAddress((void**)&q,   g_q);
    cudaGetSymbolAddress((void**)&k,   g_k);
    cudaGetSymbolAddress((void**)&v,   g_v);
    cudaGetSymbolAddress((void**)&o,   g_o);
    cudaGetSymbolAddress((void**)&ff,  g_ff);
    cudaGetSymbolAddress((void**)&att, g_att);
    cudaGetSymbolAddress((void**)&nll, g_nll);

    cudaFuncSetAttribute(gemm_tf32, cudaFuncAttributeMaxDynamicSharedMemorySize, GSMEM);
    cudaFuncSetAttribute(gemm64,    cudaFuncAttributeMaxDynamicSharedMemorySize, GSMEM64);

    embed_kernel<<<(BT * D + 255) / 256, 256>>>(idx, tok_emb, pos_emb, x);

    dim3 gD64(BT / 64, D / 64);              // 64 x 12 = 768 CTAs
    dim3 gF(BT / 128, FF / 64);              // 32 x 48
    dim3 gV(BT / 128, (VV + 63) / 64);       // 32 x 786

    for (int l = 0; l < NL; l++) {
        const float* wq = Wq + (size_t)l * D * D;
        const float* wk = Wk + (size_t)l * D * D;
        const float* wv = Wv + (size_t)l * D * D;
        const float* wo = Wo + (size_t)l * D * D;
        const float* w1 = W1 + (size_t)l * D * FF;
        const float* w2 = W2 + (size_t)l * FF * D;

        ln_kernel<<<BT, 256>>>(x, ln1_g + (size_t)l * D, ln1_b + (size_t)l * D, h);
        gemm64<<<gD64, 128, GSMEM64>>>(h, wq, nullptr, nullptr, q, BT, D, D, 0, 0);
        gemm64<<<gD64, 128, GSMEM64>>>(h, wk, nullptr, nullptr, k, BT, D, D, 0, 0);
        gemm64<<<gD64, 128, GSMEM64>>>(h, wv, nullptr, nullptr, v, BT, D, D, 0, 0);

        attn_scores<<<dim3(TT / 64, TT / 64, BH), 128>>>(q, k, att);
        attn_softmax<<<BH * TT, 256>>>(att);
        attn_pv<<<dim3(TT / 64, BH), 128>>>(att, v, o);

        gemm64<<<gD64, 128, GSMEM64>>>(o, wo, bo + (size_t)l * D, x, x, BT, D, D, 0, 0);

        ln_kernel<<<BT, 256>>>(x, ln2_g + (size_t)l * D, ln2_b + (size_t)l * D, h);
        gemm_tf32<<<gF, 128, GSMEM>>>(h, w1, b1 + (size_t)l * FF, nullptr, ff, BT, FF, D, FF, FF, 1, 1);
        gemm64<<<gD64, 128, GSMEM64>>>(ff, w2, b2 + (size_t)l * D, x, x, BT, D, FF, 0, 0);
    }

    // rounded copy of x for the LM head A operand
    round_kernel<<<1024, 256>>>(x, h, (long long)BT * D);

    float* logits = (float*)d_out;
    gemm_tf32<<<gV, 128, GSMEM>>>(h, Wlm, blm, nullptr, logits, BT, VV, D, VV, VV, 0, 0);

    long long btv = (long long)BT * VV;
    if ((long long)out_size > btv) {
        nll_kernel<<<BT, 256>>>(logits, targets, nll);
        loss_kernel<<<1, 256>>>(nll, logits + btv, (int)((long long)out_size - btv));
    }
}

// round 12
// speedup vs baseline: 1.2072x; 1.2072x over previous
#include <cuda_runtime.h>
#include <cuda_bf16.h>
#include <stdint.h>
#include <float.h>
#include <math.h>

// ---------------- problem constants ----------------
#define NL   12
#define D    768
#define NH   12
#define HD   64
#define VV   50257
#define BB   4
#define TT   1024
#define BT   (BB*TT)          // 4096
#define FF   (4*D)            // 3072
#define BH   (BB*NH)          // 48
#define EPSF 1e-5f
#define SCALE 0.125f          // HD^-0.5

// ---------------- scratch (device globals; no runtime alloc) ----------------
__device__ float g_x[BT*D];
__device__ float g_h[BT*D];
__device__ float g_q[BT*D];
__device__ float g_k[BT*D];
__device__ float g_v[BT*D];
__device__ float g_o[BT*D];
__device__ float g_ff[BT*FF];
__device__ float g_nll[BT];

// ---------------- tf32 / async helpers ----------------
__device__ __forceinline__ unsigned f2tf(float x) {
    unsigned r;
    asm("cvt.rna.tf32.f32 %0, %1;" : "=r"(r) : "f"(x));
    return r;
}
__device__ __forceinline__ float tf32f(float x) { return __uint_as_float(f2tf(x)); }

__device__ __forceinline__ void mma_tf32(float* d, const unsigned* a, const unsigned* b) {
    asm volatile(
        "mma.sync.aligned.m16n8k8.row.col.f32.tf32.tf32.f32 "
        "{%0,%1,%2,%3}, {%4,%5,%6,%7}, {%8,%9}, {%0,%1,%2,%3};"
        : "+f"(d[0]), "+f"(d[1]), "+f"(d[2]), "+f"(d[3])
        : "r"(a[0]), "r"(a[1]), "r"(a[2]), "r"(a[3]), "r"(b[0]), "r"(b[1]));
}
__device__ __forceinline__ void cp16(void* s, const void* g) {
    unsigned sa = (unsigned)__cvta_generic_to_shared(s);
    asm volatile("cp.async.cg.shared.global [%0], [%1], 16;" :: "r"(sa), "l"(g));
}
__device__ __forceinline__ void cp4z(void* s, const void* g, int srcbytes) {
    unsigned sa = (unsigned)__cvta_generic_to_shared(s);
    asm volatile("cp.async.ca.shared.global [%0], [%1], 4, %2;"
                 :: "r"(sa), "l"(g), "r"(srcbytes));
}
#define CP_COMMIT() asm volatile("cp.async.commit_group;")
#define CP_WAIT1()  asm volatile("cp.async.wait_group 1;")

// ---------------- tf32 rounding pass ----------------
__global__ void round_kernel(const float* __restrict__ in, float* __restrict__ out,
                             long long n) {
    long long i = (long long)blockIdx.x * blockDim.x + threadIdx.x;
    long long stride = (long long)gridDim.x * blockDim.x;
    for (; i < n; i += stride) out[i] = tf32f(in[i]);
}

// ---------------- embedding ----------------
__global__ void embed_kernel(const int* __restrict__ idx,
                             const float* __restrict__ tok,
                             const float* __restrict__ pos,
                             float* __restrict__ x) {
    int i = blockIdx.x * 256 + threadIdx.x;
    if (i >= BT * D) return;
    int row = i / D;
    int d   = i - row * D;
    int t   = row & (TT - 1);
    x[i] = tok[(size_t)idx[row] * D + d] + pos[(size_t)t * D + d];
}

// ---------------- layernorm (output pre-rounded to tf32) ----------------
__global__ void ln_kernel(const float* __restrict__ x,
                          const float* __restrict__ g,
                          const float* __restrict__ b,
                          float* __restrict__ out) {
    int row = blockIdx.x;
    const float* xr = x + (size_t)row * D;
    __shared__ float sx[D];
    __shared__ float red[256];
    int tid = threadIdx.x;

    float s = 0.f;
    for (int i = tid; i < D; i += 256) { float t = xr[i]; sx[i] = t; s += t; }
    red[tid] = s; __syncthreads();
    #pragma unroll
    for (int off = 128; off > 0; off >>= 1) {
        if (tid < off) red[tid] += red[tid + off];
        __syncthreads();
    }
    float mean = red[0] * (1.f / D);
    __syncthreads();

    float s2 = 0.f;
    for (int i = tid; i < D; i += 256) { float t = sx[i] - mean; s2 += t * t; }
    red[tid] = s2; __syncthreads();
    #pragma unroll
    for (int off = 128; off > 0; off >>= 1) {
        if (tid < off) red[tid] += red[tid + off];
        __syncthreads();
    }
    float rstd = rsqrtf(red[0] * (1.f / D) + EPSF);

    float* orow = out + (size_t)row * D;
    for (int i = tid; i < D; i += 256)
        orow[i] = tf32f((sx[i] - mean) * rstd * g[i] + b[i]);
}

// ---------------- TF32 GEMM, 128x64x32 block (proven R6/R8 core) ----------------
#define AK    36
#define BN2   68
#define ASTG  (128*AK)
#define BSTG  (32*BN2)
#define BOFF  (2*ASTG)
#define GSMEM ((2*ASTG + 2*BSTG) * 4)   // 54272 bytes

__global__ __launch_bounds__(128, 3)
void gemm_tf32(const float* __restrict__ A, const float* __restrict__ Bm,
               const float* __restrict__ bias, const float* __restrict__ resid,
               float* __restrict__ C, int M, int Ncols, int K, int ldB, int ldC,
               int relu, int roundC) {
    extern __shared__ float smem[];

    const int tid  = threadIdx.x;
    const int lane = tid & 31;
    const int wid  = tid >> 5;
    const int warpM = (wid >> 1) * 64;
    const int warpN = (wid & 1) * 32;
    const int gm = blockIdx.x * 128;
    const int gn = blockIdx.y * 64;
    const int lt = lane & 3;
    const int lg = lane >> 2;
    const bool alignedB = ((ldB & 3) == 0) && (gn + 64 <= ldB);

    float acc[4][4][4];
    #pragma unroll
    for (int mi = 0; mi < 4; mi++)
        #pragma unroll
        for (int nj = 0; nj < 4; nj++)
            #pragma unroll
            for (int r = 0; r < 4; r++) acc[mi][nj][r] = 0.f;

    const int nch = K >> 5;

    auto load_tiles = [&](int k0, int stage) {
        float* As = smem + stage * ASTG;
        float* Bs = smem + BOFF + stage * BSTG;
        #pragma unroll
        for (int i = 0; i < 8; i++) {
            int c  = tid + i * 128;
            int m  = c >> 3;
            int k4 = (c & 7) << 2;
            cp16(As + m * AK + k4, A + (size_t)(gm + m) * K + k0 + k4);
        }
        if (alignedB) {
            #pragma unroll
            for (int i = 0; i < 4; i++) {
                int c  = tid + i * 128;
                int kr = c >> 4;
                int n4 = (c & 15) << 2;
                cp16(Bs + kr * BN2 + n4, Bm + (size_t)(k0 + kr) * ldB + gn + n4);
            }
        } else {
            #pragma unroll
            for (int i = 0; i < 16; i++) {
                int c  = tid + i * 128;
                int kr = c >> 6;
                int n  = c & 63;
                int col = gn + n;
                cp4z(Bs + kr * BN2 + n, Bm + (size_t)(k0 + kr) * ldB + col,
                     (col < ldB) ? 4 : 0);
            }
        }
    };

    load_tiles(0, 0);
    CP_COMMIT();

    unsigned a[2][4][4], b[2][4][2];

    for (int ch = 0; ch < nch; ch++) {
        int stage = ch & 1;
        if (ch + 1 < nch) load_tiles((ch + 1) << 5, stage ^ 1);
        CP_COMMIT();
        CP_WAIT1();
        __syncthreads();

        const float* Asb = smem + stage * ASTG;
        const float* Bsb = smem + BOFF + stage * BSTG;

        auto load_frag = [&](int kk, int buf) {
            #pragma unroll
            for (int mi = 0; mi < 4; mi++) {
                const float* p0 = Asb + (warpM + mi * 16 + lg) * AK + kk;
                const float* p1 = p0 + 8 * AK;
                a[buf][mi][0] = __float_as_uint(p0[lt]);
                a[buf][mi][1] = __float_as_uint(p1[lt]);
                a[buf][mi][2] = __float_as_uint(p0[lt + 4]);
                a[buf][mi][3] = __float_as_uint(p1[lt + 4]);
            }
            #pragma unroll
            for (int nj = 0; nj < 4; nj++) {
                int nc = warpN + nj * 8 + lg;
                b[buf][nj][0] = f2tf(Bsb[(kk + lt) * BN2 + nc]);
                b[buf][nj][1] = f2tf(Bsb[(kk + lt + 4) * BN2 + nc]);
            }
        };

        load_frag(0, 0);
        #pragma unroll
        for (int kks = 0; kks < 4; kks++) {
            int cur = kks & 1;
            if (kks < 3) load_frag((kks + 1) << 3, cur ^ 1);
            #pragma unroll
            for (int mi = 0; mi < 4; mi++)
                #pragma unroll
                for (int nj = 0; nj < 4; nj++)
                    mma_tf32(acc[mi][nj], a[cur][mi], b[cur][nj]);
        }
        __syncthreads();
    }

    #pragma unroll
    for (int mi = 0; mi < 4; mi++) {
        int r0 = gm + warpM + mi * 16 + lg;
        #pragma unroll
        for (int nj = 0; nj < 4; nj++) {
            int c0 = gn + warpN + nj * 8 + (lt << 1);
            #pragma unroll
            for (int r = 0; r < 4; r++) {
                int rowg = r0 + ((r >> 1) << 3);
                int colg = c0 + (r & 1);
                if (colg < Ncols) {
                    float v = acc[mi][nj][r];
                    if (bias)   v += bias[colg];
                    if (resid)  v += resid[(size_t)rowg * ldC + colg];
                    if (relu)   v = fmaxf(v, 0.f);
                    if (roundC) v = tf32f(v);
                    C[(size_t)rowg * ldC + colg] = v;
                }
            }
        }
    }
}

// ---------------- fused flash attention (tf32 mma, online softmax) ----------------
// One CTA per (query tile tb of 64 rows, batch-head bh). 128 threads = 4 warps 2(M)x2(N).
#define FQ 68
#define FK 65
#define FV 68
#define FP 68
#define OQ  0
#define OKK (64*FQ)                 // 4352
#define OVV (OKK + 64*FK)           // 8512
#define OPP (OVV + 64*FV)           // 12864
#define ORM (OPP + 64*FP)           // 17216
#define ORS (ORM + 128)             // 17344
#define FL_SMEM ((ORS + 128) * 4)   // 69888 bytes

__global__ __launch_bounds__(128)
void flash_attn(const float* __restrict__ q, const float* __restrict__ k,
                const float* __restrict__ v, float* __restrict__ o) {
    extern __shared__ float fsm[];
    float* Qs = fsm + OQ;
    float* Ks = fsm + OKK;
    float* Vs = fsm + OVV;
    float* Ps = fsm + OPP;
    float* Rm = fsm + ORM;
    float* Rs = fsm + ORS;

    const int tb = blockIdx.x, bh = blockIdx.y;
    const int b = bh / NH, h = bh % NH;
    const int tid = threadIdx.x;
    const int lane = tid & 31, wid = tid >> 5;
    const int warpM = (wid >> 1) * 32, warpN = (wid & 1) * 32;
    const int lt = lane & 3, lg = lane >> 2;
    const int nhalf = wid & 1;

    const float* qb = q + (size_t)b * TT * D + (size_t)h * HD;
    const float* kb = k + (size_t)b * TT * D + (size_t)h * HD;
    const float* vb = v + (size_t)b * TT * D + (size_t)h * HD;

    // load Q tile [64][64] -> Qs[m][d]
    #pragma unroll
    for (int i = 0; i < 8; i++) {
        int c  = tid + i * 128;
        int m  = c >> 4;
        int d4 = (c & 15) << 2;
        *(float4*)(Qs + m * FQ + d4) =
            *(const float4*)(qb + (size_t)(tb * 64 + m) * D + d4);
    }

    float om[4], ol[4];
    float oacc[2][4][4];
    #pragma unroll
    for (int ri = 0; ri < 4; ri++) { om[ri] = -FLT_MAX; ol[ri] = 0.f; }
    #pragma unroll
    for (int mi = 0; mi < 2; mi++)
        #pragma unroll
        for (int nj = 0; nj < 4; nj++)
            #pragma unroll
            for (int r = 0; r < 4; r++) oacc[mi][nj][r] = 0.f;

    for (int sb = 0; sb <= tb; sb++) {
        __syncthreads();   // prior iter PV done (and Q loaded on first iter)

        // K tile transposed: Ks[d][s]; V tile: Vs[s][d]
        #pragma unroll
        for (int i = 0; i < 32; i++) {
            int c = tid + i * 128;
            int s = c >> 6;
            int d = c & 63;
            Ks[d * FK + s] = kb[(size_t)(sb * 64 + s) * D + d];
        }
        #pragma unroll
        for (int i = 0; i < 8; i++) {
            int c  = tid + i * 128;
            int m  = c >> 4;
            int d4 = (c & 15) << 2;
            *(float4*)(Vs + m * FV + d4) =
                *(const float4*)(vb + (size_t)(sb * 64 + m) * D + d4);
        }
        __syncthreads();

        // ---- S = Q K^T ----
        float sacc[2][4][4];
        #pragma unroll
        for (int mi = 0; mi < 2; mi++)
            #pragma unroll
            for (int nj = 0; nj < 4; nj++)
                #pragma unroll
                for (int r = 0; r < 4; r++) sacc[mi][nj][r] = 0.f;

        #pragma unroll
        for (int kk = 0; kk < 64; kk += 8) {
            unsigned afr[2][4], bfr[4][2];
            #pragma unroll
            for (int mi = 0; mi < 2; mi++) {
                const float* p0 = Qs + (warpM + mi * 16 + lg) * FQ + kk;
                const float* p1 = p0 + 8 * FQ;
                afr[mi][0] = f2tf(p0[lt]);
                afr[mi][1] = f2tf(p1[lt]);
                afr[mi][2] = f2tf(p0[lt + 4]);
                afr[mi][3] = f2tf(p1[lt + 4]);
            }
            #pragma unroll
            for (int nj = 0; nj < 4; nj++) {
                int nc = warpN + nj * 8 + lg;
                bfr[nj][0] = f2tf(Ks[(kk + lt) * FK + nc]);
                bfr[nj][1] = f2tf(Ks[(kk + lt + 4) * FK + nc]);
            }
            #pragma unroll
            for (int mi = 0; mi < 2; mi++)
                #pragma unroll
                for (int nj = 0; nj < 4; nj++)
                    mma_tf32(sacc[mi][nj], afr[mi], bfr[nj]);
        }

        // ---- scale + causal mask + per-row max ----
        float rmax[4] = {-FLT_MAX, -FLT_MAX, -FLT_MAX, -FLT_MAX};
        #pragma unroll
        for (int mi = 0; mi < 2; mi++)
            #pragma unroll
            for (int nj = 0; nj < 4; nj++)
                #pragma unroll
                for (int r = 0; r < 4; r++) {
                    int tl = warpM + mi * 16 + lg + ((r >> 1) << 3);
                    int sl = warpN + nj * 8 + (lt << 1) + (r & 1);
                    float sv = sacc[mi][nj][r] * SCALE;
                    if (sb == tb && sl > tl) sv = -1e30f;
                    sacc[mi][nj][r] = sv;
                    int ri = mi * 2 + (r >> 1);
                    rmax[ri] = fmaxf(rmax[ri], sv);
                }
        #pragma unroll
        for (int ri = 0; ri < 4; ri++) {
            rmax[ri] = fmaxf(rmax[ri], __shfl_xor_sync(0xffffffffu, rmax[ri], 1));
            rmax[ri] = fmaxf(rmax[ri], __shfl_xor_sync(0xffffffffu, rmax[ri], 2));
        }
        if (lt == 0) {
            #pragma unroll
            for (int mi = 0; mi < 2; mi++)
                #pragma unroll
                for (int rh = 0; rh < 2; rh++)
                    Rm[nhalf * 64 + warpM + mi * 16 + rh * 8 + lg] = rmax[mi * 2 + rh];
        }
        __syncthreads();

        float mnew[4], cfac[4];
        #pragma unroll
        for (int mi = 0; mi < 2; mi++)
            #pragma unroll
            for (int rh = 0; rh < 2; rh++) {
                int ri  = mi * 2 + rh;
                int row = warpM + mi * 16 + rh * 8 + lg;
                float mb = fmaxf(Rm[row], Rm[64 + row]);
                float mn = fmaxf(om[ri], mb);
                cfac[ri] = __expf(om[ri] - mn);
                mnew[ri] = mn;
            }

        // ---- P = exp(S - m), write Ps, partial row sums, rescale O ----
        float rsum[4] = {0.f, 0.f, 0.f, 0.f};
        #pragma unroll
        for (int mi = 0; mi < 2; mi++)
            #pragma unroll
            for (int nj = 0; nj < 4; nj++)
                #pragma unroll
                for (int r = 0; r < 4; r++) {
                    int ri = mi * 2 + (r >> 1);
                    float pv = __expf(sacc[mi][nj][r] - mnew[ri]);
                    int tl = warpM + mi * 16 + lg + ((r >> 1) << 3);
                    int sl = warpN + nj * 8 + (lt << 1) + (r & 1);
                    Ps[tl * FP + sl] = pv;
                    rsum[ri] += pv;
                    oacc[mi][nj][r] *= cfac[ri];
                }
        #pragma unroll
        for (int ri = 0; ri < 4; ri++) {
            rsum[ri] += __shfl_xor_sync(0xffffffffu, rsum[ri], 1);
            rsum[ri] += __shfl_xor_sync(0xffffffffu, rsum[ri], 2);
            om[ri] = mnew[ri];
        }
        if (lt == 0) {
            #pragma unroll
            for (int mi = 0; mi < 2; mi++)
                #pragma unroll
                for (int rh = 0; rh < 2; rh++)
                    Rs[nhalf * 64 + warpM + mi * 16 + rh * 8 + lg] = rsum[mi * 2 + rh];
        }
        __syncthreads();
        #pragma unroll
        for (int mi = 0; mi < 2; mi++)
            #pragma unroll
            for (int rh = 0; rh < 2; rh++) {
                int ri  = mi * 2 + rh;
                int row = warpM + mi * 16 + rh * 8 + lg;
                ol[ri] = ol[ri] * cfac[ri] + Rs[row] + Rs[64 + row];
            }

        // ---- O += P @ V ----
        #pragma unroll
        for (int kk = 0; kk < 64; kk += 8) {
            unsigned afr[2][4], bfr[4][2];
            #pragma unroll
            for (int mi = 0; mi < 2; mi++) {
                const float* p0 = Ps + (warpM + mi * 16 + lg) * FP + kk;
                const float* p1 = p0 + 8 * FP;
                afr[mi][0] = f2tf(p0[lt]);
                afr[mi][1] = f2tf(p1[lt]);
                afr[mi][2] = f2tf(p0[lt + 4]);
                afr[mi][3] = f2tf(p1[lt + 4]);
            }
            #pragma unroll
            for (int nj = 0; nj < 4; nj++) {
                int nc = warpN + nj * 8 + lg;
                bfr[nj][0] = f2tf(Vs[(kk + lt) * FV + nc]);
                bfr[nj][1] = f2tf(Vs[(kk + lt + 4) * FV + nc]);
            }
            #pragma unroll
            for (int mi = 0; mi < 2; mi++)
                #pragma unroll
                for (int nj = 0; nj < 4; nj++)
                    mma_tf32(oacc[mi][nj], afr[mi], bfr[nj]);
        }
    }

    // ---- epilogue: O / l, round to tf32 (feeds Wo GEMM A operand) ----
    float* ob = o + (size_t)(b * TT + tb * 64) * D + (size_t)h * HD;
    #pragma unroll
    for (int mi = 0; mi < 2; mi++)
        #pragma unroll
        for (int nj = 0; nj < 4; nj++)
            #pragma unroll
            for (int r = 0; r < 4; r++) {
                int ri = mi * 2 + (r >> 1);
                int tl = warpM + mi * 16 + lg + ((r >> 1) << 3);
                int dl = warpN + nj * 8 + (lt << 1) + (r & 1);
                ob[(size_t)tl * D + dl] = tf32f(oacc[mi][nj][r] / ol[ri]);
            }
}

// ---------------- per-row NLL over vocab (single pass, online logsumexp) ----------------
__global__ void nll_kernel(const float* __restrict__ logits,
                           const int* __restrict__ targets,
                           float* __restrict__ nll) {
    int row = blockIdx.x;
    const float* lr = logits + (size_t)row * VV;
    int tid = threadIdx.x;

    float m = -FLT_MAX, s = 0.f;
    for (int i = tid; i < VV; i += 256) {
        float x = lr[i];
        if (x > m) { s = s * __expf(m - x) + 1.f; m = x; }
        else        s += __expf(x - m);
    }
    __shared__ float sm[256], ss[256];
    sm[tid] = m; ss[tid] = s; __syncthreads();
    #pragma unroll
    for (int off = 128; off > 0; off >>= 1) {
        if (tid < off) {
            float m2 = sm[tid + off], s2 = ss[tid + off];
            float M = fmaxf(sm[tid], m2);
            ss[tid] = ss[tid] * __expf(sm[tid] - M) + s2 * __expf(m2 - M);
            sm[tid] = M;
        }
        __syncthreads();
    }
    if (tid == 0)
        nll[row] = sm[0] + logf(ss[0]) - lr[targets[row]];
}

__global__ void loss_kernel(const float* __restrict__ nll, float* __restrict__ dst,
                            int nextra) {
    __shared__ float red[256];
    int tid = threadIdx.x;
    float s = 0.f;
    for (int i = tid; i < BT; i += 256) s += nll[i];
    red[tid] = s; __syncthreads();
    #pragma unroll
    for (int off = 128; off > 0; off >>= 1) {
        if (tid < off) red[tid] += red[tid + off];
        __syncthreads();
    }
    if (tid == 0) {
        float loss = red[0] * (1.f / BT);
        for (int i = 0; i < nextra; i++) dst[i] = loss;
    }
}

// ---------------- launch ----------------
extern "C" void kernel_launch(void* const* d_in, const int* in_sizes, int n_in,
                              void* d_out, int out_size) {
    const int*   idx     = (const int*)  d_in[0];
    const int*   targets = (const int*)  d_in[1];
    const float* tok_emb = (const float*)d_in[2];
    const float* pos_emb = (const float*)d_in[3];
    const float* Wq      = (const float*)d_in[4];
    const float* Wk      = (const float*)d_in[5];
    const float* Wv      = (const float*)d_in[6];
    const float* Wo      = (const float*)d_in[7];
    const float* bo      = (const float*)d_in[8];
    const float* ln1_g   = (const float*)d_in[9];
    const float* ln1_b   = (const float*)d_in[10];
    const float* ln2_g   = (const float*)d_in[11];
    const float* ln2_b   = (const float*)d_in[12];
    const float* W1      = (const float*)d_in[13];
    const float* b1      = (const float*)d_in[14];
    const float* W2      = (const float*)d_in[15];
    const float* b2      = (const float*)d_in[16];
    const float* Wlm     = (const float*)d_in[17];
    const float* blm     = (const float*)d_in[18];

    float *x, *h, *q, *k, *v, *o, *ff, *nll;
    cudaGetSymbolAddress((void**)&x,   g_x);
    cudaGetSymbolAddress((void**)&h,   g_h);
    cudaGetSymbolAddress((void**)&q,   g_q);
    cudaGetSymbolAddress((void**)&k,   g_k);
    cudaGetSymbolAddress((void**)&v,   g_v);
    cudaGetSymbolAddress((void**)&o,   g_o);
    cudaGetSymbolAddress((void**)&ff,  g_ff);
    cudaGetSymbolAddress((void**)&nll, g_nll);

    cudaFuncSetAttribute(gemm_tf32,  cudaFuncAttributeMaxDynamicSharedMemorySize, GSMEM);
    cudaFuncSetAttribute(flash_attn, cudaFuncAttributeMaxDynamicSharedMemorySize, FL_SMEM);

    embed_kernel<<<(BT * D + 255) / 256, 256>>>(idx, tok_emb, pos_emb, x);

    dim3 gD(BT / 128, D / 64);               // 32 x 12
    dim3 gF(BT / 128, FF / 64);              // 32 x 48
    dim3 gV(BT / 128, (VV + 63) / 64);       // 32 x 786

    for (int l = 0; l < NL; l++) {
        const float* wq = Wq + (size_t)l * D * D;
        const float* wk = Wk + (size_t)l * D * D;
        const float* wv = Wv + (size_t)l * D * D;
        const float* wo = Wo + (size_t)l * D * D;
        const float* w1 = W1 + (size_t)l * D * FF;
        const float* w2 = W2 + (size_t)l * FF * D;

        ln_kernel<<<BT, 256>>>(x, ln1_g + (size_t)l * D, ln1_b + (size_t)l * D, h);
        gemm_tf32<<<gD, 128, GSMEM>>>(h, wq, nullptr, nullptr, q, BT, D, D, D, D, 0, 0);
        gemm_tf32<<<gD, 128, GSMEM>>>(h, wk, nullptr, nullptr, k, BT, D, D, D, D, 0, 0);
        gemm_tf32<<<gD, 128, GSMEM>>>(h, wv, nullptr, nullptr, v, BT, D, D, D, D, 0, 0);

        flash_attn<<<dim3(TT / 64, BH), 128, FL_SMEM>>>(q, k, v, o);

        gemm_tf32<<<gD, 128, GSMEM>>>(o, wo, bo + (size_t)l * D, x, x, BT, D, D, D, D, 0, 0);

        ln_kernel<<<BT, 256>>>(x, ln2_g + (size_t)l * D, ln2_b + (size_t)l * D, h);
        gemm_tf32<<<gF, 128, GSMEM>>>(h, w1, b1 + (size_t)l * FF, nullptr, ff, BT, FF, D, FF, FF, 1, 1);
        gemm_tf32<<<gD, 128, GSMEM>>>(ff, w2, b2 + (size_t)l * D, x, x, BT, D, FF, D, D, 0, 0);
    }

    // rounded copy of x for the LM head A operand
    round_kernel<<<1024, 256>>>(x, h, (long long)BT * D);

    float* logits = (float*)d_out;
    gemm_tf32<<<gV, 128, GSMEM>>>(h, Wlm, blm, nullptr, logits, BT, VV, D, VV, VV, 0, 0);

    long long btv = (long long)BT * VV;
    if ((long long)out_size > btv) {
        nll_kernel<<<BT, 256>>>(logits, targets, nll);
        loss_kernel<<<1, 256>>>(nll, logits + btv, (int)((long long)out_size - btv));
    }
}

// round 13
// speedup vs baseline: 1.2854x; 1.0648x over previous
#include <cuda_runtime.h>
#include <cuda_bf16.h>
#include <stdint.h>
#include <float.h>
#include <math.h>

// ---------------- problem constants ----------------
#define NL   12
#define D    768
#define NH   12
#define HD   64
#define VV   50257
#define BB   4
#define TT   1024
#define BT   (BB*TT)          // 4096
#define FF   (4*D)            // 3072
#define BH   (BB*NH)          // 48
#define D3   (3*D)            // 2304
#define EPSF 1e-5f
#define SCALE 0.125f          // HD^-0.5

// ---------------- scratch (device globals; no runtime alloc) ----------------
__device__ float g_x[BT*D];
__device__ float g_h[BT*D];
__device__ float g_qkv[(size_t)BT*D3];        // 37.7 MB
__device__ float g_o[BT*D];
__device__ float g_ff[BT*FF];
__device__ float g_wqkv[(size_t)NL*D*D3];     // 84.9 MB
__device__ float g_nll[BT];

// ---------------- tf32 / async helpers ----------------
__device__ __forceinline__ unsigned f2tf(float x) {
    unsigned r;
    asm("cvt.rna.tf32.f32 %0, %1;" : "=r"(r) : "f"(x));
    return r;
}
__device__ __forceinline__ float tf32f(float x) { return __uint_as_float(f2tf(x)); }

__device__ __forceinline__ void mma_tf32(float* d, const unsigned* a, const unsigned* b) {
    asm volatile(
        "mma.sync.aligned.m16n8k8.row.col.f32.tf32.tf32.f32 "
        "{%0,%1,%2,%3}, {%4,%5,%6,%7}, {%8,%9}, {%0,%1,%2,%3};"
        : "+f"(d[0]), "+f"(d[1]), "+f"(d[2]), "+f"(d[3])
        : "r"(a[0]), "r"(a[1]), "r"(a[2]), "r"(a[3]), "r"(b[0]), "r"(b[1]));
}
__device__ __forceinline__ void cp16(void* s, const void* g) {
    unsigned sa = (unsigned)__cvta_generic_to_shared(s);
    asm volatile("cp.async.cg.shared.global [%0], [%1], 16;" :: "r"(sa), "l"(g));
}
__device__ __forceinline__ void cp4z(void* s, const void* g, int srcbytes) {
    unsigned sa = (unsigned)__cvta_generic_to_shared(s);
    asm volatile("cp.async.ca.shared.global [%0], [%1], 4, %2;"
                 :: "r"(sa), "l"(g), "r"(srcbytes));
}
#define CP_COMMIT() asm volatile("cp.async.commit_group;")
#define CP_WAIT1()  asm volatile("cp.async.wait_group 1;")

// ---------------- tf32 rounding pass ----------------
__global__ void round_kernel(const float* __restrict__ in, float* __restrict__ out,
                             long long n) {
    long long i = (long long)blockIdx.x * blockDim.x + threadIdx.x;
    long long stride = (long long)gridDim.x * blockDim.x;
    for (; i < n; i += stride) out[i] = tf32f(in[i]);
}

// ---------------- QKV weight repack: wqkv[l][k][0:D)=Wq, [D:2D)=Wk, [2D:3D)=Wv ----------------
__global__ void pack_qkv_kernel(const float* __restrict__ Wq,
                                const float* __restrict__ Wk,
                                const float* __restrict__ Wv,
                                float* __restrict__ out) {
    long long i = (long long)blockIdx.x * blockDim.x + threadIdx.x;
    long long stride = (long long)gridDim.x * blockDim.x;
    long long n = (long long)NL * D * D3;
    for (; i < n; i += stride) {
        long long lk = i / D3;          // l*D + k
        int j = (int)(i - lk * D3);
        float v;
        if (j < D)        v = Wq[lk * D + j];
        else if (j < 2*D) v = Wk[lk * D + (j - D)];
        else              v = Wv[lk * D + (j - 2*D)];
        out[i] = v;
    }
}

// ---------------- embedding ----------------
__global__ void embed_kernel(const int* __restrict__ idx,
                             const float* __restrict__ tok,
                             const float* __restrict__ pos,
                             float* __restrict__ x) {
    int i = blockIdx.x * 256 + threadIdx.x;
    if (i >= BT * D) return;
    int row = i / D;
    int d   = i - row * D;
    int t   = row & (TT - 1);
    x[i] = tok[(size_t)idx[row] * D + d] + pos[(size_t)t * D + d];
}

// ---------------- layernorm (output pre-rounded to tf32) ----------------
__global__ void ln_kernel(const float* __restrict__ x,
                          const float* __restrict__ g,
                          const float* __restrict__ b,
                          float* __restrict__ out) {
    int row = blockIdx.x;
    const float* xr = x + (size_t)row * D;
    __shared__ float sx[D];
    __shared__ float red[256];
    int tid = threadIdx.x;

    float s = 0.f;
    for (int i = tid; i < D; i += 256) { float t = xr[i]; sx[i] = t; s += t; }
    red[tid] = s; __syncthreads();
    #pragma unroll
    for (int off = 128; off > 0; off >>= 1) {
        if (tid < off) red[tid] += red[tid + off];
        __syncthreads();
    }
    float mean = red[0] * (1.f / D);
    __syncthreads();

    float s2 = 0.f;
    for (int i = tid; i < D; i += 256) { float t = sx[i] - mean; s2 += t * t; }
    red[tid] = s2; __syncthreads();
    #pragma unroll
    for (int off = 128; off > 0; off >>= 1) {
        if (tid < off) red[tid] += red[tid + off];
        __syncthreads();
    }
    float rstd = rsqrtf(red[0] * (1.f / D) + EPSF);

    float* orow = out + (size_t)row * D;
    for (int i = tid; i < D; i += 256)
        orow[i] = tf32f((sx[i] - mean) * rstd * g[i] + b[i]);
}

// ---------------- TF32 GEMM, 128x64x32 block (BN2=72: conflict-free B frags) ----------------
#define AK    36
#define BN2   72
#define ASTG  (128*AK)          // 4608
#define BSTG  (32*BN2)          // 2304
#define BOFF  (2*ASTG)
#define GSMEM ((2*ASTG + 2*BSTG) * 4)   // 55296 bytes

__global__ __launch_bounds__(128, 3)
void gemm_tf32(const float* __restrict__ A, const float* __restrict__ Bm,
               const float* __restrict__ bias, const float* __restrict__ resid,
               float* __restrict__ C, int M, int Ncols, int K, int ldB, int ldC,
               int relu, int roundC) {
    extern __shared__ float smem[];

    const int tid  = threadIdx.x;
    const int lane = tid & 31;
    const int wid  = tid >> 5;
    const int warpM = (wid >> 1) * 64;
    const int warpN = (wid & 1) * 32;
    const int gm = blockIdx.x * 128;
    const int gn = blockIdx.y * 64;
    const int lt = lane & 3;
    const int lg = lane >> 2;
    const bool alignedB = ((ldB & 3) == 0) && (gn + 64 <= ldB);

    float acc[4][4][4];
    #pragma unroll
    for (int mi = 0; mi < 4; mi++)
        #pragma unroll
        for (int nj = 0; nj < 4; nj++)
            #pragma unroll
            for (int r = 0; r < 4; r++) acc[mi][nj][r] = 0.f;

    const int nch = K >> 5;

    auto load_tiles = [&](int k0, int stage) {
        float* As = smem + stage * ASTG;
        float* Bs = smem + BOFF + stage * BSTG;
        #pragma unroll
        for (int i = 0; i < 8; i++) {
            int c  = tid + i * 128;
            int m  = c >> 3;
            int k4 = (c & 7) << 2;
            cp16(As + m * AK + k4, A + (size_t)(gm + m) * K + k0 + k4);
        }
        if (alignedB) {
            #pragma unroll
            for (int i = 0; i < 4; i++) {
                int c  = tid + i * 128;
                int kr = c >> 4;
                int n4 = (c & 15) << 2;
                cp16(Bs + kr * BN2 + n4, Bm + (size_t)(k0 + kr) * ldB + gn + n4);
            }
        } else {
            #pragma unroll
            for (int i = 0; i < 16; i++) {
                int c  = tid + i * 128;
                int kr = c >> 6;
                int n  = c & 63;
                int col = gn + n;
                cp4z(Bs + kr * BN2 + n, Bm + (size_t)(k0 + kr) * ldB + col,
                     (col < ldB) ? 4 : 0);
            }
        }
    };

    load_tiles(0, 0);
    CP_COMMIT();

    unsigned a[2][4][4], b[2][4][2];

    for (int ch = 0; ch < nch; ch++) {
        int stage = ch & 1;
        if (ch + 1 < nch) load_tiles((ch + 1) << 5, stage ^ 1);
        CP_COMMIT();
        CP_WAIT1();
        __syncthreads();

        const float* Asb = smem + stage * ASTG;
        const float* Bsb = smem + BOFF + stage * BSTG;

        auto load_frag = [&](int kk, int buf) {
            #pragma unroll
            for (int mi = 0; mi < 4; mi++) {
                const float* p0 = Asb + (warpM + mi * 16 + lg) * AK + kk;
                const float* p1 = p0 + 8 * AK;
                a[buf][mi][0] = __float_as_uint(p0[lt]);
                a[buf][mi][1] = __float_as_uint(p1[lt]);
                a[buf][mi][2] = __float_as_uint(p0[lt + 4]);
                a[buf][mi][3] = __float_as_uint(p1[lt + 4]);
            }
            #pragma unroll
            for (int nj = 0; nj < 4; nj++) {
                int nc = warpN + nj * 8 + lg;
                b[buf][nj][0] = f2tf(Bsb[(kk + lt) * BN2 + nc]);
                b[buf][nj][1] = f2tf(Bsb[(kk + lt + 4) * BN2 + nc]);
            }
        };

        load_frag(0, 0);
        #pragma unroll
        for (int kks = 0; kks < 4; kks++) {
            int cur = kks & 1;
            if (kks < 3) load_frag((kks + 1) << 3, cur ^ 1);
            #pragma unroll
            for (int mi = 0; mi < 4; mi++)
                #pragma unroll
                for (int nj = 0; nj < 4; nj++)
                    mma_tf32(acc[mi][nj], a[cur][mi], b[cur][nj]);
        }
        __syncthreads();
    }

    #pragma unroll
    for (int mi = 0; mi < 4; mi++) {
        int r0 = gm + warpM + mi * 16 + lg;
        #pragma unroll
        for (int nj = 0; nj < 4; nj++) {
            int c0 = gn + warpN + nj * 8 + (lt << 1);
            #pragma unroll
            for (int r = 0; r < 4; r++) {
                int rowg = r0 + ((r >> 1) << 3);
                int colg = c0 + (r & 1);
                if (colg < Ncols) {
                    float v = acc[mi][nj][r];
                    if (bias)   v += bias[colg];
                    if (resid)  v += resid[(size_t)rowg * ldC + colg];
                    if (relu)   v = fmaxf(v, 0.f);
                    if (roundC) v = tf32f(v);
                    C[(size_t)rowg * ldC + colg] = v;
                }
            }
        }
    }
}

// ---------------- fused flash attention (tf32 mma, online softmax) ----------------
// Q/K/V packed in qkv[BT][3D]; q at +0, k at +D, v at +2D (per-head offset h*HD).
#define FQ 68
#define FK 66
#define FV 72
#define FP 68
#define OQ  0
#define OKK (64*FQ)                 // 4352
#define OVV (OKK + 64*FK)           // 8576
#define OPP (OVV + 64*FV)           // 13184
#define ORM (OPP + 64*FP)           // 17536
#define ORS (ORM + 128)             // 17664
#define FL_SMEM ((ORS + 128) * 4)   // 71168 bytes

__global__ __launch_bounds__(128)
void flash_attn(const float* __restrict__ qkv, float* __restrict__ o) {
    extern __shared__ float fsm[];
    float* Qs = fsm + OQ;
    float* Ks = fsm + OKK;
    float* Vs = fsm + OVV;
    float* Ps = fsm + OPP;
    float* Rm = fsm + ORM;
    float* Rs = fsm + ORS;

    const int tb = blockIdx.x, bh = blockIdx.y;
    const int b = bh / NH, h = bh % NH;
    const int tid = threadIdx.x;
    const int lane = tid & 31, wid = tid >> 5;
    const int warpM = (wid >> 1) * 32, warpN = (wid & 1) * 32;
    const int lt = lane & 3, lg = lane >> 2;
    const int nhalf = wid & 1;

    const float* qb = qkv + (size_t)b * TT * D3 + (size_t)h * HD;
    const float* kb = qb + D;
    const float* vb = qb + 2 * D;

    // load Q tile [64][64] -> Qs[m][d]
    #pragma unroll
    for (int i = 0; i < 8; i++) {
        int c  = tid + i * 128;
        int m  = c >> 4;
        int d4 = (c & 15) << 2;
        *(float4*)(Qs + m * FQ + d4) =
            *(const float4*)(qb + (size_t)(tb * 64 + m) * D3 + d4);
    }

    float om[4], ol[4];
    float oacc[2][4][4];
    #pragma unroll
    for (int ri = 0; ri < 4; ri++) { om[ri] = -FLT_MAX; ol[ri] = 0.f; }
    #pragma unroll
    for (int mi = 0; mi < 2; mi++)
        #pragma unroll
        for (int nj = 0; nj < 4; nj++)
            #pragma unroll
            for (int r = 0; r < 4; r++) oacc[mi][nj][r] = 0.f;

    for (int sb = 0; sb <= tb; sb++) {
        __syncthreads();

        #pragma unroll
        for (int i = 0; i < 32; i++) {
            int c = tid + i * 128;
            int s = c >> 6;
            int d = c & 63;
            Ks[d * FK + s] = kb[(size_t)(sb * 64 + s) * D3 + d];
        }
        #pragma unroll
        for (int i = 0; i < 8; i++) {
            int c  = tid + i * 128;
            int m  = c >> 4;
            int d4 = (c & 15) << 2;
            *(float4*)(Vs + m * FV + d4) =
                *(const float4*)(vb + (size_t)(sb * 64 + m) * D3 + d4);
        }
        __syncthreads();

        // ---- S = Q K^T ----
        float sacc[2][4][4];
        #pragma unroll
        for (int mi = 0; mi < 2; mi++)
            #pragma unroll
            for (int nj = 0; nj < 4; nj++)
                #pragma unroll
                for (int r = 0; r < 4; r++) sacc[mi][nj][r] = 0.f;

        #pragma unroll
        for (int kk = 0; kk < 64; kk += 8) {
            unsigned afr[2][4], bfr[4][2];
            #pragma unroll
            for (int mi = 0; mi < 2; mi++) {
                const float* p0 = Qs + (warpM + mi * 16 + lg) * FQ + kk;
                const float* p1 = p0 + 8 * FQ;
                afr[mi][0] = f2tf(p0[lt]);
                afr[mi][1] = f2tf(p1[lt]);
                afr[mi][2] = f2tf(p0[lt + 4]);
                afr[mi][3] = f2tf(p1[lt + 4]);
            }
            #pragma unroll
            for (int nj = 0; nj < 4; nj++) {
                int nc = warpN + nj * 8 + lg;
                bfr[nj][0] = f2tf(Ks[(kk + lt) * FK + nc]);
                bfr[nj][1] = f2tf(Ks[(kk + lt + 4) * FK + nc]);
            }
            #pragma unroll
            for (int mi = 0; mi < 2; mi++)
                #pragma unroll
                for (int nj = 0; nj < 4; nj++)
                    mma_tf32(sacc[mi][nj], afr[mi], bfr[nj]);
        }

        // ---- scale + causal mask + per-row max ----
        float rmax[4] = {-FLT_MAX, -FLT_MAX, -FLT_MAX, -FLT_MAX};
        #pragma unroll
        for (int mi = 0; mi < 2; mi++)
            #pragma unroll
            for (int nj = 0; nj < 4; nj++)
                #pragma unroll
                for (int r = 0; r < 4; r++) {
                    int tl = warpM + mi * 16 + lg + ((r >> 1) << 3);
                    int sl = warpN + nj * 8 + (lt << 1) + (r & 1);
                    float sv = sacc[mi][nj][r] * SCALE;
                    if (sb == tb && sl > tl) sv = -1e30f;
                    sacc[mi][nj][r] = sv;
                    int ri = mi * 2 + (r >> 1);
                    rmax[ri] = fmaxf(rmax[ri], sv);
                }
        #pragma unroll
        for (int ri = 0; ri < 4; ri++) {
            rmax[ri] = fmaxf(rmax[ri], __shfl_xor_sync(0xffffffffu, rmax[ri], 1));
            rmax[ri] = fmaxf(rmax[ri], __shfl_xor_sync(0xffffffffu, rmax[ri], 2));
        }
        if (lt == 0) {
            #pragma unroll
            for (int mi = 0; mi < 2; mi++)
                #pragma unroll
                for (int rh = 0; rh < 2; rh++)
                    Rm[nhalf * 64 + warpM + mi * 16 + rh * 8 + lg] = rmax[mi * 2 + rh];
        }
        __syncthreads();

        float mnew[4], cfac[4];
        #pragma unroll
        for (int mi = 0; mi < 2; mi++)
            #pragma unroll
            for (int rh = 0; rh < 2; rh++) {
                int ri  = mi * 2 + rh;
                int row = warpM + mi * 16 + rh * 8 + lg;
                float mb = fmaxf(Rm[row], Rm[64 + row]);
                float mn = fmaxf(om[ri], mb);
                cfac[ri] = __expf(om[ri] - mn);
                mnew[ri] = mn;
            }

        // ---- P = exp(S - m), write Ps, partial row sums, rescale O ----
        float rsum[4] = {0.f, 0.f, 0.f, 0.f};
        #pragma unroll
        for (int mi = 0; mi < 2; mi++)
            #pragma unroll
            for (int nj = 0; nj < 4; nj++)
                #pragma unroll
                for (int r = 0; r < 4; r++) {
                    int ri = mi * 2 + (r >> 1);
                    float pv = __expf(sacc[mi][nj][r] - mnew[ri]);
                    int tl = warpM + mi * 16 + lg + ((r >> 1) << 3);
                    int sl = warpN + nj * 8 + (lt << 1) + (r & 1);
                    Ps[tl * FP + sl] = pv;
                    rsum[ri] += pv;
                    oacc[mi][nj][r] *= cfac[ri];
                }
        #pragma unroll
        for (int ri = 0; ri < 4; ri++) {
            rsum[ri] += __shfl_xor_sync(0xffffffffu, rsum[ri], 1);
            rsum[ri] += __shfl_xor_sync(0xffffffffu, rsum[ri], 2);
            om[ri] = mnew[ri];
        }
        if (lt == 0) {
            #pragma unroll
            for (int mi = 0; mi < 2; mi++)
                #pragma unroll
                for (int rh = 0; rh < 2; rh++)
                    Rs[nhalf * 64 + warpM + mi * 16 + rh * 8 + lg] = rsum[mi * 2 + rh];
        }
        __syncthreads();
        #pragma unroll
        for (int mi = 0; mi < 2; mi++)
            #pragma unroll
            for (int rh = 0; rh < 2; rh++) {
                int ri  = mi * 2 + rh;
                int row = warpM + mi * 16 + rh * 8 + lg;
                ol[ri] = ol[ri] * cfac[ri] + Rs[row] + Rs[64 + row];
            }

        // ---- O += P @ V ----
        #pragma unroll
        for (int kk = 0; kk < 64; kk += 8) {
            unsigned afr[2][4], bfr[4][2];
            #pragma unroll
            for (int mi = 0; mi < 2; mi++) {
                const float* p0 = Ps + (warpM + mi * 16 + lg) * FP + kk;
                const float* p1 = p0 + 8 * FP;
                afr[mi][0] = f2tf(p0[lt]);
                afr[mi][1] = f2tf(p1[lt]);
                afr[mi][2] = f2tf(p0[lt + 4]);
                afr[mi][3] = f2tf(p1[lt + 4]);
            }
            #pragma unroll
            for (int nj = 0; nj < 4; nj++) {
                int nc = warpN + nj * 8 + lg;
                bfr[nj][0] = f2tf(Vs[(kk + lt) * FV + nc]);
                bfr[nj][1] = f2tf(Vs[(kk + lt + 4) * FV + nc]);
            }
            #pragma unroll
            for (int mi = 0; mi < 2; mi++)
                #pragma unroll
                for (int nj = 0; nj < 4; nj++)
                    mma_tf32(oacc[mi][nj], afr[mi], bfr[nj]);
        }
    }

    // ---- epilogue: O / l, round to tf32 (feeds Wo GEMM A operand) ----
    float* ob = o + (size_t)(b * TT + tb * 64) * D + (size_t)h * HD;
    #pragma unroll
    for (int mi = 0; mi < 2; mi++)
        #pragma unroll
        for (int nj = 0; nj < 4; nj++)
            #pragma unroll
            for (int r = 0; r < 4; r++) {
                int ri = mi * 2 + (r >> 1);
                int tl = warpM + mi * 16 + lg + ((r >> 1) << 3);
                int dl = warpN + nj * 8 + (lt << 1) + (r & 1);
                ob[(size_t)tl * D + dl] = tf32f(oacc[mi][nj][r] / ol[ri]);
            }
}

// ---------------- per-row NLL over vocab (single pass, online logsumexp) ----------------
__global__ void nll_kernel(const float* __restrict__ logits,
                           const int* __restrict__ targets,
                           float* __restrict__ nll) {
    int row = blockIdx.x;
    const float* lr = logits + (size_t)row * VV;
    int tid = threadIdx.x;

    float m = -FLT_MAX, s = 0.f;
    for (int i = tid; i < VV; i += 256) {
        float x = lr[i];
        if (x > m) { s = s * __expf(m - x) + 1.f; m = x; }
        else        s += __expf(x - m);
    }
    __shared__ float sm[256], ss[256];
    sm[tid] = m; ss[tid] = s; __syncthreads();
    #pragma unroll
    for (int off = 128; off > 0; off >>= 1) {
        if (tid < off) {
            float m2 = sm[tid + off], s2 = ss[tid + off];
            float M = fmaxf(sm[tid], m2);
            ss[tid] = ss[tid] * __expf(sm[tid] - M) + s2 * __expf(m2 - M);
            sm[tid] = M;
        }
        __syncthreads();
    }
    if (tid == 0)
        nll[row] = sm[0] + logf(ss[0]) - lr[targets[row]];
}

__global__ void loss_kernel(const float* __restrict__ nll, float* __restrict__ dst,
                            int nextra) {
    __shared__ float red[256];
    int tid = threadIdx.x;
    float s = 0.f;
    for (int i = tid; i < BT; i += 256) s += nll[i];
    red[tid] = s; __syncthreads();
    #pragma unroll
    for (int off = 128; off > 0; off >>= 1) {
        if (tid < off) red[tid] += red[tid + off];
        __syncthreads();
    }
    if (tid == 0) {
        float loss = red[0] * (1.f / BT);
        for (int i = 0; i < nextra; i++) dst[i] = loss;
    }
}

// ---------------- launch ----------------
extern "C" void kernel_launch(void* const* d_in, const int* in_sizes, int n_in,
                              void* d_out, int out_size) {
    const int*   idx     = (const int*)  d_in[0];
    const int*   targets = (const int*)  d_in[1];
    const float* tok_emb = (const float*)d_in[2];
    const float* pos_emb = (const float*)d_in[3];
    const float* Wq      = (const float*)d_in[4];
    const float* Wk      = (const float*)d_in[5];
    const float* Wv      = (const float*)d_in[6];
    const float* Wo      = (const float*)d_in[7];
    const float* bo      = (const float*)d_in[8];
    const float* ln1_g   = (const float*)d_in[9];
    const float* ln1_b   = (const float*)d_in[10];
    const float* ln2_g   = (const float*)d_in[11];
    const float* ln2_b   = (const float*)d_in[12];
    const float* W1      = (const float*)d_in[13];
    const float* b1      = (const float*)d_in[14];
    const float* W2      = (const float*)d_in[15];
    const float* b2      = (const float*)d_in[16];
    const float* Wlm     = (const float*)d_in[17];
    const float* blm     = (const float*)d_in[18];

    float *x, *h, *qkv, *o, *ff, *wqkv, *nll;
    cudaGetSymbolAddress((void**)&x,    g_x);
    cudaGetSymbolAddress((void**)&h,    g_h);
    cudaGetSymbolAddress((void**)&qkv,  g_qkv);
    cudaGetSymbolAddress((void**)&o,    g_o);
    cudaGetSymbolAddress((void**)&ff,   g_ff);
    cudaGetSymbolAddress((void**)&wqkv, g_wqkv);
    cudaGetSymbolAddress((void**)&nll,  g_nll);

    cudaFuncSetAttribute(gemm_tf32,  cudaFuncAttributeMaxDynamicSharedMemorySize, GSMEM);
    cudaFuncSetAttribute(flash_attn, cudaFuncAttributeMaxDynamicSharedMemorySize, FL_SMEM);

    pack_qkv_kernel<<<2048, 256>>>(Wq, Wk, Wv, wqkv);
    embed_kernel<<<(BT * D + 255) / 256, 256>>>(idx, tok_emb, pos_emb, x);

    dim3 gD(BT / 128, D / 64);               // 32 x 12
    dim3 gQKV(BT / 128, D3 / 64);            // 32 x 36
    dim3 gF(BT / 128, FF / 64);              // 32 x 48
    dim3 gV(BT / 128, (VV + 63) / 64);       // 32 x 786

    for (int l = 0; l < NL; l++) {
        const float* wqkv_l = wqkv + (size_t)l * D * D3;
        const float* wo = Wo + (size_t)l * D * D;
        const float* w1 = W1 + (size_t)l * D * FF;
        const float* w2 = W2 + (size_t)l * FF * D;

        ln_kernel<<<BT, 256>>>(x, ln1_g + (size_t)l * D, ln1_b + (size_t)l * D, h);
        gemm_tf32<<<gQKV, 128, GSMEM>>>(h, wqkv_l, nullptr, nullptr, qkv,
                                        BT, D3, D, D3, D3, 0, 0);

        flash_attn<<<dim3(TT / 64, BH), 128, FL_SMEM>>>(qkv, o);

        gemm_tf32<<<gD, 128, GSMEM>>>(o, wo, bo + (size_t)l * D, x, x,
                                      BT, D, D, D, D, 0, 0);

        ln_kernel<<<BT, 256>>>(x, ln2_g + (size_t)l * D, ln2_b + (size_t)l * D, h);
        gemm_tf32<<<gF, 128, GSMEM>>>(h, w1, b1 + (size_t)l * FF, nullptr, ff,
                                      BT, FF, D, FF, FF, 1, 1);
        gemm_tf32<<<gD, 128, GSMEM>>>(ff, w2, b2 + (size_t)l * D, x, x,
                                      BT, D, FF, D, D, 0, 0);
    }

    // rounded copy of x for the LM head A operand
    round_kernel<<<1024, 256>>>(x, h, (long long)BT * D);

    float* logits = (float*)d_out;
    gemm_tf32<<<gV, 128, GSMEM>>>(h, Wlm, blm, nullptr, logits, BT, VV, D, VV, VV, 0, 0);

    long long btv = (long long)BT * VV;
    if ((long long)out_size > btv) {
        nll_kernel<<<BT, 256>>>(logits, targets, nll);
        loss_kernel<<<1, 256>>>(nll, logits + btv, (int)((long long)out_size - btv));
    }
}

// round 14
// speedup vs baseline: 1.2992x; 1.0107x over previous
#include <cuda_runtime.h>
#include <cuda_bf16.h>
#include <stdint.h>
#include <float.h>
#include <math.h>

// ---------------- problem constants ----------------
#define NL   12
#define D    768
#define NH   12
#define HD   64
#define VV   50257
#define BB   4
#define TT   1024
#define BT   (BB*TT)          // 4096
#define FF   (4*D)            // 3072
#define BH   (BB*NH)          // 48
#define D3   (3*D)            // 2304
#define EPSF 1e-5f
#define SCALE 0.125f          // HD^-0.5

// ---------------- scratch (device globals; no runtime alloc) ----------------
__device__ float g_x[BT*D];
__device__ float g_h[BT*D];
__device__ float g_qkv[(size_t)BT*D3];        // 37.7 MB
__device__ float g_o[BT*D];
__device__ float g_ff[BT*FF];
__device__ float g_wqkv[(size_t)NL*D*D3];     // 84.9 MB
__device__ float g_nll[BT];

// ---------------- tf32 / async helpers ----------------
__device__ __forceinline__ unsigned f2tf(float x) {
    unsigned r;
    asm("cvt.rna.tf32.f32 %0, %1;" : "=r"(r) : "f"(x));
    return r;
}
__device__ __forceinline__ float tf32f(float x) { return __uint_as_float(f2tf(x)); }

__device__ __forceinline__ void mma_tf32(float* d, const unsigned* a, const unsigned* b) {
    asm volatile(
        "mma.sync.aligned.m16n8k8.row.col.f32.tf32.tf32.f32 "
        "{%0,%1,%2,%3}, {%4,%5,%6,%7}, {%8,%9}, {%0,%1,%2,%3};"
        : "+f"(d[0]), "+f"(d[1]), "+f"(d[2]), "+f"(d[3])
        : "r"(a[0]), "r"(a[1]), "r"(a[2]), "r"(a[3]), "r"(b[0]), "r"(b[1]));
}
__device__ __forceinline__ void cp16(void* s, const void* g) {
    unsigned sa = (unsigned)__cvta_generic_to_shared(s);
    asm volatile("cp.async.cg.shared.global [%0], [%1], 16;" :: "r"(sa), "l"(g));
}
__device__ __forceinline__ void cp4z(void* s, const void* g, int srcbytes) {
    unsigned sa = (unsigned)__cvta_generic_to_shared(s);
    asm volatile("cp.async.ca.shared.global [%0], [%1], 4, %2;"
                 :: "r"(sa), "l"(g), "r"(srcbytes));
}
#define CP_COMMIT() asm volatile("cp.async.commit_group;")
#define CP_WAIT1()  asm volatile("cp.async.wait_group 1;")

// ---------------- tf32 rounding pass ----------------
__global__ void round_kernel(const float* __restrict__ in, float* __restrict__ out,
                             long long n) {
    long long i = (long long)blockIdx.x * blockDim.x + threadIdx.x;
    long long stride = (long long)gridDim.x * blockDim.x;
    for (; i < n; i += stride) out[i] = tf32f(in[i]);
}

// ---------------- QKV weight repack ----------------
__global__ void pack_qkv_kernel(const float* __restrict__ Wq,
                                const float* __restrict__ Wk,
                                const float* __restrict__ Wv,
                                float* __restrict__ out) {
    long long i = (long long)blockIdx.x * blockDim.x + threadIdx.x;
    long long stride = (long long)gridDim.x * blockDim.x;
    long long n = (long long)NL * D * D3;
    for (; i < n; i += stride) {
        long long lk = i / D3;
        int j = (int)(i - lk * D3);
        float v;
        if (j < D)        v = Wq[lk * D + j];
        else if (j < 2*D) v = Wk[lk * D + (j - D)];
        else              v = Wv[lk * D + (j - 2*D)];
        out[i] = v;
    }
}

// ---------------- embedding ----------------
__global__ void embed_kernel(const int* __restrict__ idx,
                             const float* __restrict__ tok,
                             const float* __restrict__ pos,
                             float* __restrict__ x) {
    int i = blockIdx.x * 256 + threadIdx.x;
    if (i >= BT * D) return;
    int row = i / D;
    int d   = i - row * D;
    int t   = row & (TT - 1);
    x[i] = tok[(size_t)idx[row] * D + d] + pos[(size_t)t * D + d];
}

// ---------------- layernorm (output pre-rounded to tf32) ----------------
__global__ void ln_kernel(const float* __restrict__ x,
                          const float* __restrict__ g,
                          const float* __restrict__ b,
                          float* __restrict__ out) {
    int row = blockIdx.x;
    const float* xr = x + (size_t)row * D;
    __shared__ float sx[D];
    __shared__ float red[256];
    int tid = threadIdx.x;

    float s = 0.f;
    for (int i = tid; i < D; i += 256) { float t = xr[i]; sx[i] = t; s += t; }
    red[tid] = s; __syncthreads();
    #pragma unroll
    for (int off = 128; off > 0; off >>= 1) {
        if (tid < off) red[tid] += red[tid + off];
        __syncthreads();
    }
    float mean = red[0] * (1.f / D);
    __syncthreads();

    float s2 = 0.f;
    for (int i = tid; i < D; i += 256) { float t = sx[i] - mean; s2 += t * t; }
    red[tid] = s2; __syncthreads();
    #pragma unroll
    for (int off = 128; off > 0; off >>= 1) {
        if (tid < off) red[tid] += red[tid + off];
        __syncthreads();
    }
    float rstd = rsqrtf(red[0] * (1.f / D) + EPSF);

    float* orow = out + (size_t)row * D;
    for (int i = tid; i < D; i += 256)
        orow[i] = tf32f((sx[i] - mean) * rstd * g[i] + b[i]);
}

// ---------------- TF32 GEMM, 128x64x32 block; single-buffer frags, 4 CTAs/SM ----------------
#define AK    36
#define BN2   72
#define ASTG  (128*AK)          // 4608
#define BSTG  (32*BN2)          // 2304
#define BOFF  (2*ASTG)
#define GSMEM ((2*ASTG + 2*BSTG) * 4)   // 55296 bytes

__global__ __launch_bounds__(128, 4)
void gemm_tf32(const float* __restrict__ A, const float* __restrict__ Bm,
               const float* __restrict__ bias, const float* __restrict__ resid,
               float* __restrict__ C, int M, int Ncols, int K, int ldB, int ldC,
               int relu, int roundC) {
    extern __shared__ float smem[];

    const int tid  = threadIdx.x;
    const int lane = tid & 31;
    const int wid  = tid >> 5;
    const int warpM = (wid >> 1) * 64;
    const int warpN = (wid & 1) * 32;
    const int gm = blockIdx.x * 128;
    const int gn = blockIdx.y * 64;
    const int lt = lane & 3;
    const int lg = lane >> 2;
    const bool alignedB = ((ldB & 3) == 0) && (gn + 64 <= ldB);

    float acc[4][4][4];
    #pragma unroll
    for (int mi = 0; mi < 4; mi++)
        #pragma unroll
        for (int nj = 0; nj < 4; nj++)
            #pragma unroll
            for (int r = 0; r < 4; r++) acc[mi][nj][r] = 0.f;

    const int nch = K >> 5;

    auto load_tiles = [&](int k0, int stage) {
        float* As = smem + stage * ASTG;
        float* Bs = smem + BOFF + stage * BSTG;
        #pragma unroll
        for (int i = 0; i < 8; i++) {
            int c  = tid + i * 128;
            int m  = c >> 3;
            int k4 = (c & 7) << 2;
            cp16(As + m * AK + k4, A + (size_t)(gm + m) * K + k0 + k4);
        }
        if (alignedB) {
            #pragma unroll
            for (int i = 0; i < 4; i++) {
                int c  = tid + i * 128;
                int kr = c >> 4;
                int n4 = (c & 15) << 2;
                cp16(Bs + kr * BN2 + n4, Bm + (size_t)(k0 + kr) * ldB + gn + n4);
            }
        } else {
            #pragma unroll
            for (int i = 0; i < 16; i++) {
                int c  = tid + i * 128;
                int kr = c >> 6;
                int n  = c & 63;
                int col = gn + n;
                cp4z(Bs + kr * BN2 + n, Bm + (size_t)(k0 + kr) * ldB + col,
                     (col < ldB) ? 4 : 0);
            }
        }
    };

    load_tiles(0, 0);
    CP_COMMIT();

    for (int ch = 0; ch < nch; ch++) {
        int stage = ch & 1;
        if (ch + 1 < nch) load_tiles((ch + 1) << 5, stage ^ 1);
        CP_COMMIT();
        CP_WAIT1();
        __syncthreads();

        const float* Asb = smem + stage * ASTG;
        const float* Bsb = smem + BOFF + stage * BSTG;

        #pragma unroll
        for (int kk = 0; kk < 32; kk += 8) {
            unsigned a[4][4], b[4][2];
            #pragma unroll
            for (int mi = 0; mi < 4; mi++) {
                const float* p0 = Asb + (warpM + mi * 16 + lg) * AK + kk;
                const float* p1 = p0 + 8 * AK;
                a[mi][0] = __float_as_uint(p0[lt]);
                a[mi][1] = __float_as_uint(p1[lt]);
                a[mi][2] = __float_as_uint(p0[lt + 4]);
                a[mi][3] = __float_as_uint(p1[lt + 4]);
            }
            #pragma unroll
            for (int nj = 0; nj < 4; nj++) {
                int nc = warpN + nj * 8 + lg;
                b[nj][0] = f2tf(Bsb[(kk + lt) * BN2 + nc]);
                b[nj][1] = f2tf(Bsb[(kk + lt + 4) * BN2 + nc]);
            }
            #pragma unroll
            for (int mi = 0; mi < 4; mi++)
                #pragma unroll
                for (int nj = 0; nj < 4; nj++)
                    mma_tf32(acc[mi][nj], a[mi], b[nj]);
        }
        __syncthreads();
    }

    #pragma unroll
    for (int mi = 0; mi < 4; mi++) {
        int r0 = gm + warpM + mi * 16 + lg;
        #pragma unroll
        for (int nj = 0; nj < 4; nj++) {
            int c0 = gn + warpN + nj * 8 + (lt << 1);
            #pragma unroll
            for (int r = 0; r < 4; r++) {
                int rowg = r0 + ((r >> 1) << 3);
                int colg = c0 + (r & 1);
                if (colg < Ncols) {
                    float v = acc[mi][nj][r];
                    if (bias)   v += bias[colg];
                    if (resid)  v += resid[(size_t)rowg * ldC + colg];
                    if (relu)   v = fmaxf(v, 0.f);
                    if (roundC) v = tf32f(v);
                    C[(size_t)rowg * ldC + colg] = v;
                }
            }
        }
    }
}

// ---------------- fused flash attention (tf32 mma, online softmax) ----------------
// Q/K/V packed in qkv[BT][3D]; q at +0, k at +D, v at +2D (per-head offset h*HD).
#define FQ 68
#define FK 72
#define FV 72
#define FP 68
#define OQ  0
#define OKK (64*FQ)                 // 4352
#define OVV (OKK + 64*FK)           // 8960
#define OPP (OVV + 64*FV)           // 13568
#define ORM (OPP + 64*FP)           // 17920
#define ORS (ORM + 128)             // 18048
#define FL_SMEM ((ORS + 128) * 4)   // 72704 bytes

__global__ __launch_bounds__(128)
void flash_attn(const float* __restrict__ qkv, float* __restrict__ o) {
    extern __shared__ float fsm[];
    float* Qs = fsm + OQ;
    float* Ks = fsm + OKK;
    float* Vs = fsm + OVV;
    float* Ps = fsm + OPP;
    float* Rm = fsm + ORM;
    float* Rs = fsm + ORS;

    const int tb = blockIdx.x, bh = blockIdx.y;
    const int b = bh / NH, h = bh % NH;
    const int tid = threadIdx.x;
    const int lane = tid & 31, wid = tid >> 5;
    const int warpM = (wid >> 1) * 32, warpN = (wid & 1) * 32;
    const int lt = lane & 3, lg = lane >> 2;
    const int nhalf = wid & 1;

    const float* qb = qkv + (size_t)b * TT * D3 + (size_t)h * HD;
    const float* kb = qb + D;
    const float* vb = qb + 2 * D;

    #pragma unroll
    for (int i = 0; i < 8; i++) {
        int c  = tid + i * 128;
        int m  = c >> 4;
        int d4 = (c & 15) << 2;
        *(float4*)(Qs + m * FQ + d4) =
            *(const float4*)(qb + (size_t)(tb * 64 + m) * D3 + d4);
    }

    float om[4], ol[4];
    float oacc[2][4][4];
    #pragma unroll
    for (int ri = 0; ri < 4; ri++) { om[ri] = -FLT_MAX; ol[ri] = 0.f; }
    #pragma unroll
    for (int mi = 0; mi < 2; mi++)
        #pragma unroll
        for (int nj = 0; nj < 4; nj++)
            #pragma unroll
            for (int r = 0; r < 4; r++) oacc[mi][nj][r] = 0.f;

    for (int sb = 0; sb <= tb; sb++) {
        __syncthreads();

        #pragma unroll
        for (int i = 0; i < 32; i++) {
            int c = tid + i * 128;
            int s = c >> 6;
            int d = c & 63;
            Ks[d * FK + s] = kb[(size_t)(sb * 64 + s) * D3 + d];
        }
        #pragma unroll
        for (int i = 0; i < 8; i++) {
            int c  = tid + i * 128;
            int m  = c >> 4;
            int d4 = (c & 15) << 2;
            *(float4*)(Vs + m * FV + d4) =
                *(const float4*)(vb + (size_t)(sb * 64 + m) * D3 + d4);
        }
        __syncthreads();

        // ---- S = Q K^T ----
        float sacc[2][4][4];
        #pragma unroll
        for (int mi = 0; mi < 2; mi++)
            #pragma unroll
            for (int nj = 0; nj < 4; nj++)
                #pragma unroll
                for (int r = 0; r < 4; r++) sacc[mi][nj][r] = 0.f;

        #pragma unroll
        for (int kk = 0; kk < 64; kk += 8) {
            unsigned afr[2][4], bfr[4][2];
            #pragma unroll
            for (int mi = 0; mi < 2; mi++) {
                const float* p0 = Qs + (warpM + mi * 16 + lg) * FQ + kk;
                const float* p1 = p0 + 8 * FQ;
                afr[mi][0] = f2tf(p0[lt]);
                afr[mi][1] = f2tf(p1[lt]);
                afr[mi][2] = f2tf(p0[lt + 4]);
                afr[mi][3] = f2tf(p1[lt + 4]);
            }
            #pragma unroll
            for (int nj = 0; nj < 4; nj++) {
                int nc = warpN + nj * 8 + lg;
                bfr[nj][0] = f2tf(Ks[(kk + lt) * FK + nc]);
                bfr[nj][1] = f2tf(Ks[(kk + lt + 4) * FK + nc]);
            }
            #pragma unroll
            for (int mi = 0; mi < 2; mi++)
                #pragma unroll
                for (int nj = 0; nj < 4; nj++)
                    mma_tf32(sacc[mi][nj], afr[mi], bfr[nj]);
        }

        // ---- scale + causal mask + per-row max ----
        float rmax[4] = {-FLT_MAX, -FLT_MAX, -FLT_MAX, -FLT_MAX};
        #pragma unroll
        for (int mi = 0; mi < 2; mi++)
            #pragma unroll
            for (int nj = 0; nj < 4; nj++)
                #pragma unroll
                for (int r = 0; r < 4; r++) {
                    int tl = warpM + mi * 16 + lg + ((r >> 1) << 3);
                    int sl = warpN + nj * 8 + (lt << 1) + (r & 1);
                    float sv = sacc[mi][nj][r] * SCALE;
                    if (sb == tb && sl > tl) sv = -1e30f;
                    sacc[mi][nj][r] = sv;
                    int ri = mi * 2 + (r >> 1);
                    rmax[ri] = fmaxf(rmax[ri], sv);
                }
        #pragma unroll
        for (int ri = 0; ri < 4; ri++) {
            rmax[ri] = fmaxf(rmax[ri], __shfl_xor_sync(0xffffffffu, rmax[ri], 1));
            rmax[ri] = fmaxf(rmax[ri], __shfl_xor_sync(0xffffffffu, rmax[ri], 2));
        }
        if (lt == 0) {
            #pragma unroll
            for (int mi = 0; mi < 2; mi++)
                #pragma unroll
                for (int rh = 0; rh < 2; rh++)
                    Rm[nhalf * 64 + warpM + mi * 16 + rh * 8 + lg] = rmax[mi * 2 + rh];
        }
        __syncthreads();

        float mnew[4], cfac[4];
        #pragma unroll
        for (int mi = 0; mi < 2; mi++)
            #pragma unroll
            for (int rh = 0; rh < 2; rh++) {
                int ri  = mi * 2 + rh;
                int row = warpM + mi * 16 + rh * 8 + lg;
                float mb = fmaxf(Rm[row], Rm[64 + row]);
                float mn = fmaxf(om[ri], mb);
                cfac[ri] = __expf(om[ri] - mn);
                mnew[ri] = mn;
            }

        // ---- P = exp(S - m), write Ps, partial row sums, rescale O ----
        float rsum[4] = {0.f, 0.f, 0.f, 0.f};
        #pragma unroll
        for (int mi = 0; mi < 2; mi++)
            #pragma unroll
            for (int nj = 0; nj < 4; nj++)
                #pragma unroll
                for (int r = 0; r < 4; r++) {
                    int ri = mi * 2 + (r >> 1);
                    float pv = __expf(sacc[mi][nj][r] - mnew[ri]);
                    int tl = warpM + mi * 16 + lg + ((r >> 1) << 3);
                    int sl = warpN + nj * 8 + (lt << 1) + (r & 1);
                    Ps[tl * FP + sl] = pv;
                    rsum[ri] += pv;
                    oacc[mi][nj][r] *= cfac[ri];
                }
        #pragma unroll
        for (int ri = 0; ri < 4; ri++) {
            rsum[ri] += __shfl_xor_sync(0xffffffffu, rsum[ri], 1);
            rsum[ri] += __shfl_xor_sync(0xffffffffu, rsum[ri], 2);
            om[ri] = mnew[ri];
        }
        if (lt == 0) {
            #pragma unroll
            for (int mi = 0; mi < 2; mi++)
                #pragma unroll
                for (int rh = 0; rh < 2; rh++)
                    Rs[nhalf * 64 + warpM + mi * 16 + rh * 8 + lg] = rsum[mi * 2 + rh];
        }
        __syncthreads();
        #pragma unroll
        for (int mi = 0; mi < 2; mi++)
            #pragma unroll
            for (int rh = 0; rh < 2; rh++) {
                int ri  = mi * 2 + rh;
                int row = warpM + mi * 16 + rh * 8 + lg;
                ol[ri] = ol[ri] * cfac[ri] + Rs[row] + Rs[64 + row];
            }

        // ---- O += P @ V ----
        #pragma unroll
        for (int kk = 0; kk < 64; kk += 8) {
            unsigned afr[2][4], bfr[4][2];
            #pragma unroll
            for (int mi = 0; mi < 2; mi++) {
                const float* p0 = Ps + (warpM + mi * 16 + lg) * FP + kk;
                const float* p1 = p0 + 8 * FP;
                afr[mi][0] = f2tf(p0[lt]);
                afr[mi][1] = f2tf(p1[lt]);
                afr[mi][2] = f2tf(p0[lt + 4]);
                afr[mi][3] = f2tf(p1[lt + 4]);
            }
            #pragma unroll
            for (int nj = 0; nj < 4; nj++) {
                int nc = warpN + nj * 8 + lg;
                bfr[nj][0] = f2tf(Vs[(kk + lt) * FV + nc]);
                bfr[nj][1] = f2tf(Vs[(kk + lt + 4) * FV + nc]);
            }
            #pragma unroll
            for (int mi = 0; mi < 2; mi++)
                #pragma unroll
                for (int nj = 0; nj < 4; nj++)
                    mma_tf32(oacc[mi][nj], afr[mi], bfr[nj]);
        }
    }

    // ---- epilogue: O / l, round to tf32 (feeds Wo GEMM A operand) ----
    float* ob = o + (size_t)(b * TT + tb * 64) * D + (size_t)h * HD;
    #pragma unroll
    for (int mi = 0; mi < 2; mi++)
        #pragma unroll
        for (int nj = 0; nj < 4; nj++)
            #pragma unroll
            for (int r = 0; r < 4; r++) {
                int ri = mi * 2 + (r >> 1);
                int tl = warpM + mi * 16 + lg + ((r >> 1) << 3);
                int dl = warpN + nj * 8 + (lt << 1) + (r & 1);
                ob[(size_t)tl * D + dl] = tf32f(oacc[mi][nj][r] / ol[ri]);
            }
}

// ---------------- per-row NLL over vocab (single pass, online logsumexp) ----------------
__global__ void nll_kernel(const float* __restrict__ logits,
                           const int* __restrict__ targets,
                           float* __restrict__ nll) {
    int row = blockIdx.x;
    const float* lr = logits + (size_t)row * VV;
    int tid = threadIdx.x;

    float m = -FLT_MAX, s = 0.f;
    for (int i = tid; i < VV; i += 256) {
        float x = lr[i];
        if (x > m) { s = s * __expf(m - x) + 1.f; m = x; }
        else        s += __expf(x - m);
    }
    __shared__ float sm[256], ss[256];
    sm[tid] = m; ss[tid] = s; __syncthreads();
    #pragma unroll
    for (int off = 128; off > 0; off >>= 1) {
        if (tid < off) {
            float m2 = sm[tid + off], s2 = ss[tid + off];
            float M = fmaxf(sm[tid], m2);
            ss[tid] = ss[tid] * __expf(sm[tid] - M) + s2 * __expf(m2 - M);
            sm[tid] = M;
        }
        __syncthreads();
    }
    if (tid == 0)
        nll[row] = sm[0] + logf(ss[0]) - lr[targets[row]];
}

__global__ void loss_kernel(const float* __restrict__ nll, float* __restrict__ dst,
                            int nextra) {
    __shared__ float red[256];
    int tid = threadIdx.x;
    float s = 0.f;
    for (int i = tid; i < BT; i += 256) s += nll[i];
    red[tid] = s; __syncthreads();
    #pragma unroll
    for (int off = 128; off > 0; off >>= 1) {
        if (tid < off) red[tid] += red[tid + off];
        __syncthreads();
    }
    if (tid == 0) {
        float loss = red[0] * (1.f / BT);
        for (int i = 0; i < nextra; i++) dst[i] = loss;
    }
}

// ---------------- launch ----------------
extern "C" void kernel_launch(void* const* d_in, const int* in_sizes, int n_in,
                              void* d_out, int out_size) {
    const int*   idx     = (const int*)  d_in[0];
    const int*   targets = (const int*)  d_in[1];
    const float* tok_emb = (const float*)d_in[2];
    const float* pos_emb = (const float*)d_in[3];
    const float* Wq      = (const float*)d_in[4];
    const float* Wk      = (const float*)d_in[5];
    const float* Wv      = (const float*)d_in[6];
    const float* Wo      = (const float*)d_in[7];
    const float* bo      = (const float*)d_in[8];
    const float* ln1_g   = (const float*)d_in[9];
    const float* ln1_b   = (const float*)d_in[10];
    const float* ln2_g   = (const float*)d_in[11];
    const float* ln2_b   = (const float*)d_in[12];
    const float* W1      = (const float*)d_in[13];
    const float* b1      = (const float*)d_in[14];
    const float* W2      = (const float*)d_in[15];
    const float* b2      = (const float*)d_in[16];
    const float* Wlm     = (const float*)d_in[17];
    const float* blm     = (const float*)d_in[18];

    float *x, *h, *qkv, *o, *ff, *wqkv, *nll;
    cudaGetSymbolAddress((void**)&x,    g_x);
    cudaGetSymbolAddress((void**)&h,    g_h);
    cudaGetSymbolAddress((void**)&qkv,  g_qkv);
    cudaGetSymbolAddress((void**)&o,    g_o);
    cudaGetSymbolAddress((void**)&ff,   g_ff);
    cudaGetSymbolAddress((void**)&wqkv, g_wqkv);
    cudaGetSymbolAddress((void**)&nll,  g_nll);

    cudaFuncSetAttribute(gemm_tf32,  cudaFuncAttributeMaxDynamicSharedMemorySize, GSMEM);
    cudaFuncSetAttribute(flash_attn, cudaFuncAttributeMaxDynamicSharedMemorySize, FL_SMEM);

    pack_qkv_kernel<<<2048, 256>>>(Wq, Wk, Wv, wqkv);
    embed_kernel<<<(BT * D + 255) / 256, 256>>>(idx, tok_emb, pos_emb, x);

    dim3 gD(BT / 128, D / 64);               // 32 x 12
    dim3 gQKV(BT / 128, D3 / 64);            // 32 x 36
    dim3 gF(BT / 128, FF / 64);              // 32 x 48
    dim3 gV(BT / 128, (VV + 63) / 64);       // 32 x 786

    for (int l = 0; l < NL; l++) {
        const float* wqkv_l = wqkv + (size_t)l * D * D3;
        const float* wo = Wo + (size_t)l * D * D;
        const float* w1 = W1 + (size_t)l * D * FF;
        const float* w2 = W2 + (size_t)l * FF * D;

        ln_kernel<<<BT, 256>>>(x, ln1_g + (size_t)l * D, ln1_b + (size_t)l * D, h);
        gemm_tf32<<<gQKV, 128, GSMEM>>>(h, wqkv_l, nullptr, nullptr, qkv,
                                        BT, D3, D, D3, D3, 0, 0);

        flash_attn<<<dim3(TT / 64, BH), 128, FL_SMEM>>>(qkv, o);

        gemm_tf32<<<gD, 128, GSMEM>>>(o, wo, bo + (size_t)l * D, x, x,
                                      BT, D, D, D, D, 0, 0);

        ln_kernel<<<BT, 256>>>(x, ln2_g + (size_t)l * D, ln2_b + (size_t)l * D, h);
        gemm_tf32<<<gF, 128, GSMEM>>>(h, w1, b1 + (size_t)l * FF, nullptr, ff,
                                      BT, FF, D, FF, FF, 1, 1);
        gemm_tf32<<<gD, 128, GSMEM>>>(ff, w2, b2 + (size_t)l * D, x, x,
                                      BT, D, FF, D, D, 0, 0);
    }

    // rounded copy of x for the LM head A operand
    round_kernel<<<1024, 256>>>(x, h, (long long)BT * D);

    float* logits = (float*)d_out;
    gemm_tf32<<<gV, 128, GSMEM>>>(h, Wlm, blm, nullptr, logits, BT, VV, D, VV, VV, 0, 0);

    long long btv = (long long)BT * VV;
    if ((long long)out_size > btv) {
        nll_kernel<<<BT, 256>>>(logits, targets, nll);
        loss_kernel<<<1, 256>>>(nll, logits + btv, (int)((long long)out_size - btv));
    }
}

// round 15
// speedup vs baseline: 1.3270x; 1.0214x over previous
#include <cuda_runtime.h>
#include <cuda_bf16.h>
#include <stdint.h>
#include <float.h>
#include <math.h>

// ---------------- problem constants ----------------
#define NL   12
#define D    768
#define NH   12
#define HD   64
#define VV   50257
#define BB   4
#define TT   1024
#define BT   (BB*TT)          // 4096
#define FF   (4*D)            // 3072
#define BH   (BB*NH)          // 48
#define D3   (3*D)            // 2304
#define EPSF 1e-5f
#define SCALE 0.125f          // HD^-0.5

// ---------------- scratch (device globals; no runtime alloc) ----------------
__device__ float g_x[BT*D];
__device__ float g_h[BT*D];
__device__ float g_qkv[(size_t)BT*D3];        // 37.7 MB
__device__ float g_o[BT*D];
__device__ float g_ff[BT*FF];
__device__ float g_wqkv[(size_t)NL*D*D3];     // 84.9 MB
__device__ float g_nll[BT];

// ---------------- tf32 / async helpers ----------------
__device__ __forceinline__ unsigned f2tf(float x) {
    unsigned r;
    asm("cvt.rna.tf32.f32 %0, %1;" : "=r"(r) : "f"(x));
    return r;
}
__device__ __forceinline__ float tf32f(float x) { return __uint_as_float(f2tf(x)); }

__device__ __forceinline__ void mma_tf32(float* d, const unsigned* a, const unsigned* b) {
    asm volatile(
        "mma.sync.aligned.m16n8k8.row.col.f32.tf32.tf32.f32 "
        "{%0,%1,%2,%3}, {%4,%5,%6,%7}, {%8,%9}, {%0,%1,%2,%3};"
        : "+f"(d[0]), "+f"(d[1]), "+f"(d[2]), "+f"(d[3])
        : "r"(a[0]), "r"(a[1]), "r"(a[2]), "r"(a[3]), "r"(b[0]), "r"(b[1]));
}
__device__ __forceinline__ void cp16(void* s, const void* g) {
    unsigned sa = (unsigned)__cvta_generic_to_shared(s);
    asm volatile("cp.async.cg.shared.global [%0], [%1], 16;" :: "r"(sa), "l"(g));
}
__device__ __forceinline__ void cp4z(void* s, const void* g, int srcbytes) {
    unsigned sa = (unsigned)__cvta_generic_to_shared(s);
    asm volatile("cp.async.ca.shared.global [%0], [%1], 4, %2;"
                 :: "r"(sa), "l"(g), "r"(srcbytes));
}
#define CP_COMMIT() asm volatile("cp.async.commit_group;")
#define CP_WAIT1()  asm volatile("cp.async.wait_group 1;")

// ---------------- QKV weight repack ----------------
__global__ void pack_qkv_kernel(const float* __restrict__ Wq,
                                const float* __restrict__ Wk,
                                const float* __restrict__ Wv,
                                float* __restrict__ out) {
    long long i = (long long)blockIdx.x * blockDim.x + threadIdx.x;
    long long stride = (long long)gridDim.x * blockDim.x;
    long long n = (long long)NL * D * D3;
    for (; i < n; i += stride) {
        long long lk = i / D3;
        int j = (int)(i - lk * D3);
        float v;
        if (j < D)        v = Wq[lk * D + j];
        else if (j < 2*D) v = Wk[lk * D + (j - D)];
        else              v = Wv[lk * D + (j - 2*D)];
        out[i] = v;
    }
}

// ---------------- embedding ----------------
__global__ void embed_kernel(const int* __restrict__ idx,
                             const float* __restrict__ tok,
                             const float* __restrict__ pos,
                             float* __restrict__ x) {
    int i = blockIdx.x * 256 + threadIdx.x;
    if (i >= BT * D) return;
    int row = i / D;
    int d   = i - row * D;
    int t   = row & (TT - 1);
    x[i] = tok[(size_t)idx[row] * D + d] + pos[(size_t)t * D + d];
}

// ---------------- layernorm: one warp per row, shuffle reductions ----------------
// 256 threads = 8 warps = 8 rows per block; grid = BT/8.
__global__ __launch_bounds__(256)
void ln_kernel(const float* __restrict__ x,
               const float* __restrict__ g,
               const float* __restrict__ b,
               float* __restrict__ out) {
    const int lane = threadIdx.x & 31;
    const int row  = blockIdx.x * 8 + (threadIdx.x >> 5);
    const float* xr = x + (size_t)row * D;

    float4 v[6];
    float s = 0.f;
    #pragma unroll
    for (int j = 0; j < 6; j++) {
        v[j] = *(const float4*)(xr + ((j * 32 + lane) << 2));
        s += (v[j].x + v[j].y) + (v[j].z + v[j].w);
    }
    #pragma unroll
    for (int off = 16; off > 0; off >>= 1)
        s += __shfl_xor_sync(0xffffffffu, s, off);
    float mean = s * (1.f / D);

    float s2 = 0.f;
    #pragma unroll
    for (int j = 0; j < 6; j++) {
        float d0 = v[j].x - mean, d1 = v[j].y - mean;
        float d2 = v[j].z - mean, d3 = v[j].w - mean;
        s2 += (d0 * d0 + d1 * d1) + (d2 * d2 + d3 * d3);
    }
    #pragma unroll
    for (int off = 16; off > 0; off >>= 1)
        s2 += __shfl_xor_sync(0xffffffffu, s2, off);
    float rstd = rsqrtf(s2 * (1.f / D) + EPSF);

    float* orow = out + (size_t)row * D;
    #pragma unroll
    for (int j = 0; j < 6; j++) {
        int base = (j * 32 + lane) << 2;
        float4 gv = *(const float4*)(g + base);
        float4 bv = *(const float4*)(b + base);
        float4 ov;
        ov.x = tf32f((v[j].x - mean) * rstd * gv.x + bv.x);
        ov.y = tf32f((v[j].y - mean) * rstd * gv.y + bv.y);
        ov.z = tf32f((v[j].z - mean) * rstd * gv.z + bv.z);
        ov.w = tf32f((v[j].w - mean) * rstd * gv.w + bv.w);
        *(float4*)(orow + base) = ov;
    }
}

// ---------------- TF32 GEMM, 128x64x32 block; single-buffer frags, 4 CTAs/SM ----------------
#define AK    36
#define BN2   72
#define ASTG  (128*AK)          // 4608
#define BSTG  (32*BN2)          // 2304
#define BOFF  (2*ASTG)
#define GSMEM ((2*ASTG + 2*BSTG) * 4)   // 55296 bytes

__global__ __launch_bounds__(128, 4)
void gemm_tf32(const float* __restrict__ A, const float* __restrict__ Bm,
               const float* __restrict__ bias, const float* __restrict__ resid,
               float* __restrict__ C, int M, int Ncols, int K, int ldB, int ldC,
               int relu, int roundC) {
    extern __shared__ float smem[];

    const int tid  = threadIdx.x;
    const int lane = tid & 31;
    const int wid  = tid >> 5;
    const int warpM = (wid >> 1) * 64;
    const int warpN = (wid & 1) * 32;
    const int gm = blockIdx.x * 128;
    const int gn = blockIdx.y * 64;
    const int lt = lane & 3;
    const int lg = lane >> 2;
    const bool alignedB = ((ldB & 3) == 0) && (gn + 64 <= ldB);

    float acc[4][4][4];
    #pragma unroll
    for (int mi = 0; mi < 4; mi++)
        #pragma unroll
        for (int nj = 0; nj < 4; nj++)
            #pragma unroll
            for (int r = 0; r < 4; r++) acc[mi][nj][r] = 0.f;

    const int nch = K >> 5;

    auto load_tiles = [&](int k0, int stage) {
        float* As = smem + stage * ASTG;
        float* Bs = smem + BOFF + stage * BSTG;
        #pragma unroll
        for (int i = 0; i < 8; i++) {
            int c  = tid + i * 128;
            int m  = c >> 3;
            int k4 = (c & 7) << 2;
            cp16(As + m * AK + k4, A + (size_t)(gm + m) * K + k0 + k4);
        }
        if (alignedB) {
            #pragma unroll
            for (int i = 0; i < 4; i++) {
                int c  = tid + i * 128;
                int kr = c >> 4;
                int n4 = (c & 15) << 2;
                cp16(Bs + kr * BN2 + n4, Bm + (size_t)(k0 + kr) * ldB + gn + n4);
            }
        } else {
            #pragma unroll
            for (int i = 0; i < 16; i++) {
                int c  = tid + i * 128;
                int kr = c >> 6;
                int n  = c & 63;
                int col = gn + n;
                cp4z(Bs + kr * BN2 + n, Bm + (size_t)(k0 + kr) * ldB + col,
                     (col < ldB) ? 4 : 0);
            }
        }
    };

    load_tiles(0, 0);
    CP_COMMIT();

    for (int ch = 0; ch < nch; ch++) {
        int stage = ch & 1;
        if (ch + 1 < nch) load_tiles((ch + 1) << 5, stage ^ 1);
        CP_COMMIT();
        CP_WAIT1();
        __syncthreads();

        const float* Asb = smem + stage * ASTG;
        const float* Bsb = smem + BOFF + stage * BSTG;

        #pragma unroll
        for (int kk = 0; kk < 32; kk += 8) {
            unsigned a[4][4], b[4][2];
            #pragma unroll
            for (int mi = 0; mi < 4; mi++) {
                const float* p0 = Asb + (warpM + mi * 16 + lg) * AK + kk;
                const float* p1 = p0 + 8 * AK;
                a[mi][0] = __float_as_uint(p0[lt]);
                a[mi][1] = __float_as_uint(p1[lt]);
                a[mi][2] = __float_as_uint(p0[lt + 4]);
                a[mi][3] = __float_as_uint(p1[lt + 4]);
            }
            #pragma unroll
            for (int nj = 0; nj < 4; nj++) {
                int nc = warpN + nj * 8 + lg;
                b[nj][0] = f2tf(Bsb[(kk + lt) * BN2 + nc]);
                b[nj][1] = f2tf(Bsb[(kk + lt + 4) * BN2 + nc]);
            }
            #pragma unroll
            for (int mi = 0; mi < 4; mi++)
                #pragma unroll
                for (int nj = 0; nj < 4; nj++)
                    mma_tf32(acc[mi][nj], a[mi], b[nj]);
        }
        __syncthreads();
    }

    #pragma unroll
    for (int mi = 0; mi < 4; mi++) {
        int r0 = gm + warpM + mi * 16 + lg;
        #pragma unroll
        for (int nj = 0; nj < 4; nj++) {
            int c0 = gn + warpN + nj * 8 + (lt << 1);
            #pragma unroll
            for (int r = 0; r < 4; r++) {
                int rowg = r0 + ((r >> 1) << 3);
                int colg = c0 + (r & 1);
                if (colg < Ncols) {
                    float v = acc[mi][nj][r];
                    if (bias)   v += bias[colg];
                    if (resid)  v += resid[(size_t)rowg * ldC + colg];
                    if (relu)   v = fmaxf(v, 0.f);
                    if (roundC) v = tf32f(v);
                    C[(size_t)rowg * ldC + colg] = v;
                }
            }
        }
    }
}

// ---------------- fused flash attention (tf32 mma, online softmax) ----------------
#define FQ 68
#define FK 72
#define FV 72
#define FP 68
#define OQ  0
#define OKK (64*FQ)                 // 4352
#define OVV (OKK + 64*FK)           // 8960
#define OPP (OVV + 64*FV)           // 13568
#define ORM (OPP + 64*FP)           // 17920
#define ORS (ORM + 128)             // 18048
#define FL_SMEM ((ORS + 128) * 4)   // 72704 bytes

__global__ __launch_bounds__(128)
void flash_attn(const float* __restrict__ qkv, float* __restrict__ o) {
    extern __shared__ float fsm[];
    float* Qs = fsm + OQ;
    float* Ks = fsm + OKK;
    float* Vs = fsm + OVV;
    float* Ps = fsm + OPP;
    float* Rm = fsm + ORM;
    float* Rs = fsm + ORS;

    const int tb = blockIdx.x, bh = blockIdx.y;
    const int b = bh / NH, h = bh % NH;
    const int tid = threadIdx.x;
    const int lane = tid & 31, wid = tid >> 5;
    const int warpM = (wid >> 1) * 32, warpN = (wid & 1) * 32;
    const int lt = lane & 3, lg = lane >> 2;
    const int nhalf = wid & 1;

    const float* qb = qkv + (size_t)b * TT * D3 + (size_t)h * HD;
    const float* kb = qb + D;
    const float* vb = qb + 2 * D;

    #pragma unroll
    for (int i = 0; i < 8; i++) {
        int c  = tid + i * 128;
        int m  = c >> 4;
        int d4 = (c & 15) << 2;
        *(float4*)(Qs + m * FQ + d4) =
            *(const float4*)(qb + (size_t)(tb * 64 + m) * D3 + d4);
    }

    float om[4], ol[4];
    float oacc[2][4][4];
    #pragma unroll
    for (int ri = 0; ri < 4; ri++) { om[ri] = -FLT_MAX; ol[ri] = 0.f; }
    #pragma unroll
    for (int mi = 0; mi < 2; mi++)
        #pragma unroll
        for (int nj = 0; nj < 4; nj++)
            #pragma unroll
            for (int r = 0; r < 4; r++) oacc[mi][nj][r] = 0.f;

    for (int sb = 0; sb <= tb; sb++) {
        __syncthreads();

        #pragma unroll
        for (int i = 0; i < 32; i++) {
            int c = tid + i * 128;
            int s = c >> 6;
            int d = c & 63;
            Ks[d * FK + s] = kb[(size_t)(sb * 64 + s) * D3 + d];
        }
        #pragma unroll
        for (int i = 0; i < 8; i++) {
            int c  = tid + i * 128;
            int m  = c >> 4;
            int d4 = (c & 15) << 2;
            *(float4*)(Vs + m * FV + d4) =
                *(const float4*)(vb + (size_t)(sb * 64 + m) * D3 + d4);
        }
        __syncthreads();

        float sacc[2][4][4];
        #pragma unroll
        for (int mi = 0; mi < 2; mi++)
            #pragma unroll
            for (int nj = 0; nj < 4; nj++)
                #pragma unroll
                for (int r = 0; r < 4; r++) sacc[mi][nj][r] = 0.f;

        #pragma unroll
        for (int kk = 0; kk < 64; kk += 8) {
            unsigned afr[2][4], bfr[4][2];
            #pragma unroll
            for (int mi = 0; mi < 2; mi++) {
                const float* p0 = Qs + (warpM + mi * 16 + lg) * FQ + kk;
                const float* p1 = p0 + 8 * FQ;
                afr[mi][0] = f2tf(p0[lt]);
                afr[mi][1] = f2tf(p1[lt]);
                afr[mi][2] = f2tf(p0[lt + 4]);
                afr[mi][3] = f2tf(p1[lt + 4]);
            }
            #pragma unroll
            for (int nj = 0; nj < 4; nj++) {
                int nc = warpN + nj * 8 + lg;
                bfr[nj][0] = f2tf(Ks[(kk + lt) * FK + nc]);
                bfr[nj][1] = f2tf(Ks[(kk + lt + 4) * FK + nc]);
            }
            #pragma unroll
            for (int mi = 0; mi < 2; mi++)
                #pragma unroll
                for (int nj = 0; nj < 4; nj++)
                    mma_tf32(sacc[mi][nj], afr[mi], bfr[nj]);
        }

        float rmax[4] = {-FLT_MAX, -FLT_MAX, -FLT_MAX, -FLT_MAX};
        #pragma unroll
        for (int mi = 0; mi < 2; mi++)
            #pragma unroll
            for (int nj = 0; nj < 4; nj++)
                #pragma unroll
                for (int r = 0; r < 4; r++) {
                    int tl = warpM + mi * 16 + lg + ((r >> 1) << 3);
                    int sl = warpN + nj * 8 + (lt << 1) + (r & 1);
                    float sv = sacc[mi][nj][r] * SCALE;
                    if (sb == tb && sl > tl) sv = -1e30f;
                    sacc[mi][nj][r] = sv;
                    int ri = mi * 2 + (r >> 1);
                    rmax[ri] = fmaxf(rmax[ri], sv);
                }
        #pragma unroll
        for (int ri = 0; ri < 4; ri++) {
            rmax[ri] = fmaxf(rmax[ri], __shfl_xor_sync(0xffffffffu, rmax[ri], 1));
            rmax[ri] = fmaxf(rmax[ri], __shfl_xor_sync(0xffffffffu, rmax[ri], 2));
        }
        if (lt == 0) {
            #pragma unroll
            for (int mi = 0; mi < 2; mi++)
                #pragma unroll
                for (int rh = 0; rh < 2; rh++)
                    Rm[nhalf * 64 + warpM + mi * 16 + rh * 8 + lg] = rmax[mi * 2 + rh];
        }
        __syncthreads();

        float mnew[4], cfac[4];
        #pragma unroll
        for (int mi = 0; mi < 2; mi++)
            #pragma unroll
            for (int rh = 0; rh < 2; rh++) {
                int ri  = mi * 2 + rh;
                int row = warpM + mi * 16 + rh * 8 + lg;
                float mb = fmaxf(Rm[row], Rm[64 + row]);
                float mn = fmaxf(om[ri], mb);
                cfac[ri] = __expf(om[ri] - mn);
                mnew[ri] = mn;
            }

        float rsum[4] = {0.f, 0.f, 0.f, 0.f};
        #pragma unroll
        for (int mi = 0; mi < 2; mi++)
            #pragma unroll
            for (int nj = 0; nj < 4; nj++)
                #pragma unroll
                for (int r = 0; r < 4; r++) {
                    int ri = mi * 2 + (r >> 1);
                    float pv = __expf(sacc[mi][nj][r] - mnew[ri]);
                    int tl = warpM + mi * 16 + lg + ((r >> 1) << 3);
                    int sl = warpN + nj * 8 + (lt << 1) + (r & 1);
                    Ps[tl * FP + sl] = pv;
                    rsum[ri] += pv;
                    oacc[mi][nj][r] *= cfac[ri];
                }
        #pragma unroll
        for (int ri = 0; ri < 4; ri++) {
            rsum[ri] += __shfl_xor_sync(0xffffffffu, rsum[ri], 1);
            rsum[ri] += __shfl_xor_sync(0xffffffffu, rsum[ri], 2);
            om[ri] = mnew[ri];
        }
        if (lt == 0) {
            #pragma unroll
            for (int mi = 0; mi < 2; mi++)
                #pragma unroll
                for (int rh = 0; rh < 2; rh++)
                    Rs[nhalf * 64 + warpM + mi * 16 + rh * 8 + lg] = rsum[mi * 2 + rh];
        }
        __syncthreads();
        #pragma unroll
        for (int mi = 0; mi < 2; mi++)
            #pragma unroll
            for (int rh = 0; rh < 2; rh++) {
                int ri  = mi * 2 + rh;
                int row = warpM + mi * 16 + rh * 8 + lg;
                ol[ri] = ol[ri] * cfac[ri] + Rs[row] + Rs[64 + row];
            }

        #pragma unroll
        for (int kk = 0; kk < 64; kk += 8) {
            unsigned afr[2][4], bfr[4][2];
            #pragma unroll
            for (int mi = 0; mi < 2; mi++) {
                const float* p0 = Ps + (warpM + mi * 16 + lg) * FP + kk;
                const float* p1 = p0 + 8 * FP;
                afr[mi][0] = f2tf(p0[lt]);
                afr[mi][1] = f2tf(p1[lt]);
                afr[mi][2] = f2tf(p0[lt + 4]);
                afr[mi][3] = f2tf(p1[lt + 4]);
            }
            #pragma unroll
            for (int nj = 0; nj < 4; nj++) {
                int nc = warpN + nj * 8 + lg;
                bfr[nj][0] = f2tf(Vs[(kk + lt) * FV + nc]);
                bfr[nj][1] = f2tf(Vs[(kk + lt + 4) * FV + nc]);
            }
            #pragma unroll
            for (int mi = 0; mi < 2; mi++)
                #pragma unroll
                for (int nj = 0; nj < 4; nj++)
                    mma_tf32(oacc[mi][nj], afr[mi], bfr[nj]);
        }
    }

    float* ob = o + (size_t)(b * TT + tb * 64) * D + (size_t)h * HD;
    #pragma unroll
    for (int mi = 0; mi < 2; mi++)
        #pragma unroll
        for (int nj = 0; nj < 4; nj++)
            #pragma unroll
            for (int r = 0; r < 4; r++) {
                int ri = mi * 2 + (r >> 1);
                int tl = warpM + mi * 16 + lg + ((r >> 1) << 3);
                int dl = warpN + nj * 8 + (lt << 1) + (r & 1);
                ob[(size_t)tl * D + dl] = tf32f(oacc[mi][nj][r] / ol[ri]);
            }
}

// ---------------- per-row NLL over vocab (single pass, online logsumexp) ----------------
__global__ void nll_kernel(const float* __restrict__ logits,
                           const int* __restrict__ targets,
                           float* __restrict__ nll) {
    int row = blockIdx.x;
    const float* lr = logits + (size_t)row * VV;
    int tid = threadIdx.x;

    float m = -FLT_MAX, s = 0.f;
    for (int i = tid; i < VV; i += 256) {
        float x = lr[i];
        if (x > m) { s = s * __expf(m - x) + 1.f; m = x; }
        else        s += __expf(x - m);
    }
    __shared__ float sm[256], ss[256];
    sm[tid] = m; ss[tid] = s; __syncthreads();
    #pragma unroll
    for (int off = 128; off > 0; off >>= 1) {
        if (tid < off) {
            float m2 = sm[tid + off], s2 = ss[tid + off];
            float M = fmaxf(sm[tid], m2);
            ss[tid] = ss[tid] * __expf(sm[tid] - M) + s2 * __expf(m2 - M);
            sm[tid] = M;
        }
        __syncthreads();
    }
    if (tid == 0)
        nll[row] = sm[0] + logf(ss[0]) - lr[targets[row]];
}

__global__ void loss_kernel(const float* __restrict__ nll, float* __restrict__ dst,
                            int nextra) {
    __shared__ float red[256];
    int tid = threadIdx.x;
    float s = 0.f;
    for (int i = tid; i < BT; i += 256) s += nll[i];
    red[tid] = s; __syncthreads();
    #pragma unroll
    for (int off = 128; off > 0; off >>= 1) {
        if (tid < off) red[tid] += red[tid + off];
        __syncthreads();
    }
    if (tid == 0) {
        float loss = red[0] * (1.f / BT);
        for (int i = 0; i < nextra; i++) dst[i] = loss;
    }
}

// ---------------- launch ----------------
extern "C" void kernel_launch(void* const* d_in, const int* in_sizes, int n_in,
                              void* d_out, int out_size) {
    const int*   idx     = (const int*)  d_in[0];
    const int*   targets = (const int*)  d_in[1];
    const float* tok_emb = (const float*)d_in[2];
    const float* pos_emb = (const float*)d_in[3];
    const float* Wq      = (const float*)d_in[4];
    const float* Wk      = (const float*)d_in[5];
    const float* Wv      = (const float*)d_in[6];
    const float* Wo      = (const float*)d_in[7];
    const float* bo      = (const float*)d_in[8];
    const float* ln1_g   = (const float*)d_in[9];
    const float* ln1_b   = (const float*)d_in[10];
    const float* ln2_g   = (const float*)d_in[11];
    const float* ln2_b   = (const float*)d_in[12];
    const float* W1      = (const float*)d_in[13];
    const float* b1      = (const float*)d_in[14];
    const float* W2      = (const float*)d_in[15];
    const float* b2      = (const float*)d_in[16];
    const float* Wlm     = (const float*)d_in[17];
    const float* blm     = (const float*)d_in[18];

    float *x, *h, *qkv, *o, *ff, *wqkv, *nll;
    cudaGetSymbolAddress((void**)&x,    g_x);
    cudaGetSymbolAddress((void**)&h,    g_h);
    cudaGetSymbolAddress((void**)&qkv,  g_qkv);
    cudaGetSymbolAddress((void**)&o,    g_o);
    cudaGetSymbolAddress((void**)&ff,   g_ff);
    cudaGetSymbolAddress((void**)&wqkv, g_wqkv);
    cudaGetSymbolAddress((void**)&nll,  g_nll);

    cudaFuncSetAttribute(gemm_tf32,  cudaFuncAttributeMaxDynamicSharedMemorySize, GSMEM);
    cudaFuncSetAttribute(flash_attn, cudaFuncAttributeMaxDynamicSharedMemorySize, FL_SMEM);

    pack_qkv_kernel<<<2048, 256>>>(Wq, Wk, Wv, wqkv);
    embed_kernel<<<(BT * D + 255) / 256, 256>>>(idx, tok_emb, pos_emb, x);

    dim3 gD(BT / 128, D / 64);               // 32 x 12
    dim3 gQKV(BT / 128, D3 / 64);            // 32 x 36
    dim3 gF(BT / 128, FF / 64);              // 32 x 48
    dim3 gV(BT / 128, (VV + 63) / 64);       // 32 x 786

    for (int l = 0; l < NL; l++) {
        const float* wqkv_l = wqkv + (size_t)l * D * D3;
        const float* wo = Wo + (size_t)l * D * D;
        const float* w1 = W1 + (size_t)l * D * FF;
        const float* w2 = W2 + (size_t)l * FF * D;
        int lastFF2 = (l == NL - 1) ? 1 : 0;   // round x for LM-head A operand

        ln_kernel<<<BT / 8, 256>>>(x, ln1_g + (size_t)l * D, ln1_b + (size_t)l * D, h);
        gemm_tf32<<<gQKV, 128, GSMEM>>>(h, wqkv_l, nullptr, nullptr, qkv,
                                        BT, D3, D, D3, D3, 0, 0);

        flash_attn<<<dim3(TT / 64, BH), 128, FL_SMEM>>>(qkv, o);

        gemm_tf32<<<gD, 128, GSMEM>>>(o, wo, bo + (size_t)l * D, x, x,
                                      BT, D, D, D, D, 0, 0);

        ln_kernel<<<BT / 8, 256>>>(x, ln2_g + (size_t)l * D, ln2_b + (size_t)l * D, h);
        gemm_tf32<<<gF, 128, GSMEM>>>(h, w1, b1 + (size_t)l * FF, nullptr, ff,
                                      BT, FF, D, FF, FF, 1, 1);
        gemm_tf32<<<gD, 128, GSMEM>>>(ff, w2, b2 + (size_t)l * D, x, x,
                                      BT, D, FF, D, D, 0, lastFF2);
    }

    float* logits = (float*)d_out;
    gemm_tf32<<<gV, 128, GSMEM>>>(x, Wlm, blm, nullptr, logits, BT, VV, D, VV, VV, 0, 0);

    long long btv = (long long)BT * VV;
    if ((long long)out_size > btv) {
        nll_kernel<<<BT, 256>>>(logits, targets, nll);
        loss_kernel<<<1, 256>>>(nll, logits + btv, (int)((long long)out_size - btv));
    }
}

// round 16
// speedup vs baseline: 1.3449x; 1.0135x over previous
#include <cuda_runtime.h>
#include <cuda_bf16.h>
#include <stdint.h>
#include <float.h>
#include <math.h>

// ---------------- problem constants ----------------
#define NL   12
#define D    768
#define NH   12
#define HD   64
#define VV   50257
#define BB   4
#define TT   1024
#define BT   (BB*TT)          // 4096
#define FF   (4*D)            // 3072
#define BH   (BB*NH)          // 48
#define D3   (3*D)            // 2304
#define NHALF 1572            // ceil(VV/64)*2 column-half partials per row
#define EPSF 1e-5f
#define SCALE 0.125f          // HD^-0.5

// ---------------- scratch (device globals; no runtime alloc) ----------------
__device__ float g_x[BT*D];
__device__ float g_h[BT*D];
__device__ float g_qkv[(size_t)BT*D3];        // 37.7 MB
__device__ float g_o[BT*D];
__device__ float g_ff[BT*FF];
__device__ float g_wqkv[(size_t)NL*D*D3];     // 84.9 MB
__device__ float2 g_part[(size_t)BT*NHALF];   // 51.5 MB logsumexp partials
__device__ float g_nll[BT];

// ---------------- tf32 / async helpers ----------------
__device__ __forceinline__ unsigned f2tf(float x) {
    unsigned r;
    asm("cvt.rna.tf32.f32 %0, %1;" : "=r"(r) : "f"(x));
    return r;
}
__device__ __forceinline__ float tf32f(float x) { return __uint_as_float(f2tf(x)); }

__device__ __forceinline__ void mma_tf32(float* d, const unsigned* a, const unsigned* b) {
    asm volatile(
        "mma.sync.aligned.m16n8k8.row.col.f32.tf32.tf32.f32 "
        "{%0,%1,%2,%3}, {%4,%5,%6,%7}, {%8,%9}, {%0,%1,%2,%3};"
        : "+f"(d[0]), "+f"(d[1]), "+f"(d[2]), "+f"(d[3])
        : "r"(a[0]), "r"(a[1]), "r"(a[2]), "r"(a[3]), "r"(b[0]), "r"(b[1]));
}
__device__ __forceinline__ void cp16(void* s, const void* g) {
    unsigned sa = (unsigned)__cvta_generic_to_shared(s);
    asm volatile("cp.async.cg.shared.global [%0], [%1], 16;" :: "r"(sa), "l"(g));
}
__device__ __forceinline__ void cp4z(void* s, const void* g, int srcbytes) {
    unsigned sa = (unsigned)__cvta_generic_to_shared(s);
    asm volatile("cp.async.ca.shared.global [%0], [%1], 4, %2;"
                 :: "r"(sa), "l"(g), "r"(srcbytes));
}
#define CP_COMMIT() asm volatile("cp.async.commit_group;")
#define CP_WAIT1()  asm volatile("cp.async.wait_group 1;")

// ---------------- QKV weight repack ----------------
__global__ void pack_qkv_kernel(const float* __restrict__ Wq,
                                const float* __restrict__ Wk,
                                const float* __restrict__ Wv,
                                float* __restrict__ out) {
    long long i = (long long)blockIdx.x * blockDim.x + threadIdx.x;
    long long stride = (long long)gridDim.x * blockDim.x;
    long long n = (long long)NL * D * D3;
    for (; i < n; i += stride) {
        long long lk = i / D3;
        int j = (int)(i - lk * D3);
        float v;
        if (j < D)        v = Wq[lk * D + j];
        else if (j < 2*D) v = Wk[lk * D + (j - D)];
        else              v = Wv[lk * D + (j - 2*D)];
        out[i] = v;
    }
}

// ---------------- embedding ----------------
__global__ void embed_kernel(const int* __restrict__ idx,
                             const float* __restrict__ tok,
                             const float* __restrict__ pos,
                             float* __restrict__ x) {
    int i = blockIdx.x * 256 + threadIdx.x;
    if (i >= BT * D) return;
    int row = i / D;
    int d   = i - row * D;
    int t   = row & (TT - 1);
    x[i] = tok[(size_t)idx[row] * D + d] + pos[(size_t)t * D + d];
}

// ---------------- layernorm: one warp per row, shuffle reductions ----------------
__global__ __launch_bounds__(256)
void ln_kernel(const float* __restrict__ x,
               const float* __restrict__ g,
               const float* __restrict__ b,
               float* __restrict__ out) {
    const int lane = threadIdx.x & 31;
    const int row  = blockIdx.x * 8 + (threadIdx.x >> 5);
    const float* xr = x + (size_t)row * D;

    float4 v[6];
    float s = 0.f;
    #pragma unroll
    for (int j = 0; j < 6; j++) {
        v[j] = *(const float4*)(xr + ((j * 32 + lane) << 2));
        s += (v[j].x + v[j].y) + (v[j].z + v[j].w);
    }
    #pragma unroll
    for (int off = 16; off > 0; off >>= 1)
        s += __shfl_xor_sync(0xffffffffu, s, off);
    float mean = s * (1.f / D);

    float s2 = 0.f;
    #pragma unroll
    for (int j = 0; j < 6; j++) {
        float d0 = v[j].x - mean, d1 = v[j].y - mean;
        float d2 = v[j].z - mean, d3 = v[j].w - mean;
        s2 += (d0 * d0 + d1 * d1) + (d2 * d2 + d3 * d3);
    }
    #pragma unroll
    for (int off = 16; off > 0; off >>= 1)
        s2 += __shfl_xor_sync(0xffffffffu, s2, off);
    float rstd = rsqrtf(s2 * (1.f / D) + EPSF);

    float* orow = out + (size_t)row * D;
    #pragma unroll
    for (int j = 0; j < 6; j++) {
        int base = (j * 32 + lane) << 2;
        float4 gv = *(const float4*)(g + base);
        float4 bv = *(const float4*)(b + base);
        float4 ov;
        ov.x = tf32f((v[j].x - mean) * rstd * gv.x + bv.x);
        ov.y = tf32f((v[j].y - mean) * rstd * gv.y + bv.y);
        ov.z = tf32f((v[j].z - mean) * rstd * gv.z + bv.z);
        ov.w = tf32f((v[j].w - mean) * rstd * gv.w + bv.w);
        *(float4*)(orow + base) = ov;
    }
}

// ---------------- TF32 GEMM, 128x64x32 block; single-buffer frags, 4 CTAs/SM ----------------
#define AK    36
#define BN2   72
#define ASTG  (128*AK)          // 4608
#define BSTG  (32*BN2)          // 2304
#define BOFF  (2*ASTG)
#define GSMEM ((2*ASTG + 2*BSTG) * 4)   // 55296 bytes

__global__ __launch_bounds__(128, 4)
void gemm_tf32(const float* __restrict__ A, const float* __restrict__ Bm,
               const float* __restrict__ bias, const float* __restrict__ resid,
               float* __restrict__ C, int M, int Ncols, int K, int ldB, int ldC,
               int relu, int roundC) {
    extern __shared__ float smem[];

    const int tid  = threadIdx.x;
    const int lane = tid & 31;
    const int wid  = tid >> 5;
    const int warpM = (wid >> 1) * 64;
    const int warpN = (wid & 1) * 32;
    const int gm = blockIdx.x * 128;
    const int gn = blockIdx.y * 64;
    const int lt = lane & 3;
    const int lg = lane >> 2;
    const bool alignedB = ((ldB & 3) == 0) && (gn + 64 <= ldB);

    float acc[4][4][4];
    #pragma unroll
    for (int mi = 0; mi < 4; mi++)
        #pragma unroll
        for (int nj = 0; nj < 4; nj++)
            #pragma unroll
            for (int r = 0; r < 4; r++) acc[mi][nj][r] = 0.f;

    const int nch = K >> 5;

    auto load_tiles = [&](int k0, int stage) {
        float* As = smem + stage * ASTG;
        float* Bs = smem + BOFF + stage * BSTG;
        #pragma unroll
        for (int i = 0; i < 8; i++) {
            int c  = tid + i * 128;
            int m  = c >> 3;
            int k4 = (c & 7) << 2;
            cp16(As + m * AK + k4, A + (size_t)(gm + m) * K + k0 + k4);
        }
        if (alignedB) {
            #pragma unroll
            for (int i = 0; i < 4; i++) {
                int c  = tid + i * 128;
                int kr = c >> 4;
                int n4 = (c & 15) << 2;
                cp16(Bs + kr * BN2 + n4, Bm + (size_t)(k0 + kr) * ldB + gn + n4);
            }
        } else {
            #pragma unroll
            for (int i = 0; i < 16; i++) {
                int c  = tid + i * 128;
                int kr = c >> 6;
                int n  = c & 63;
                int col = gn + n;
                cp4z(Bs + kr * BN2 + n, Bm + (size_t)(k0 + kr) * ldB + col,
                     (col < ldB) ? 4 : 0);
            }
        }
    };

    load_tiles(0, 0);
    CP_COMMIT();

    for (int ch = 0; ch < nch; ch++) {
        int stage = ch & 1;
        if (ch + 1 < nch) load_tiles((ch + 1) << 5, stage ^ 1);
        CP_COMMIT();
        CP_WAIT1();
        __syncthreads();

        const float* Asb = smem + stage * ASTG;
        const float* Bsb = smem + BOFF + stage * BSTG;

        #pragma unroll
        for (int kk = 0; kk < 32; kk += 8) {
            unsigned a[4][4], b[4][2];
            #pragma unroll
            for (int mi = 0; mi < 4; mi++) {
                const float* p0 = Asb + (warpM + mi * 16 + lg) * AK + kk;
                const float* p1 = p0 + 8 * AK;
                a[mi][0] = __float_as_uint(p0[lt]);
                a[mi][1] = __float_as_uint(p1[lt]);
                a[mi][2] = __float_as_uint(p0[lt + 4]);
                a[mi][3] = __float_as_uint(p1[lt + 4]);
            }
            #pragma unroll
            for (int nj = 0; nj < 4; nj++) {
                int nc = warpN + nj * 8 + lg;
                b[nj][0] = f2tf(Bsb[(kk + lt) * BN2 + nc]);
                b[nj][1] = f2tf(Bsb[(kk + lt + 4) * BN2 + nc]);
            }
            #pragma unroll
            for (int mi = 0; mi < 4; mi++)
                #pragma unroll
                for (int nj = 0; nj < 4; nj++)
                    mma_tf32(acc[mi][nj], a[mi], b[nj]);
        }
        __syncthreads();
    }

    #pragma unroll
    for (int mi = 0; mi < 4; mi++) {
        int r0 = gm + warpM + mi * 16 + lg;
        #pragma unroll
        for (int nj = 0; nj < 4; nj++) {
            int c0 = gn + warpN + nj * 8 + (lt << 1);
            #pragma unroll
            for (int r = 0; r < 4; r++) {
                int rowg = r0 + ((r >> 1) << 3);
                int colg = c0 + (r & 1);
                if (colg < Ncols) {
                    float v = acc[mi][nj][r];
                    if (bias)   v += bias[colg];
                    if (resid)  v += resid[(size_t)rowg * ldC + colg];
                    if (relu)   v = fmaxf(v, 0.f);
                    if (roundC) v = tf32f(v);
                    C[(size_t)rowg * ldC + colg] = v;
                }
            }
        }
    }
}

// ---------------- LM-head GEMM clone with fused logsumexp partials ----------------
// C = A[BT,K] @ B[K,Ncols] + bias; writes float2 (max, expsum) per (row, 32-col half).
__global__ __launch_bounds__(128, 4)
void gemm_lm(const float* __restrict__ A, const float* __restrict__ Bm,
             const float* __restrict__ bias, float* __restrict__ C,
             int Ncols, int K, int ldB, float2* __restrict__ part) {
    extern __shared__ float smem[];

    const int tid  = threadIdx.x;
    const int lane = tid & 31;
    const int wid  = tid >> 5;
    const int warpM = (wid >> 1) * 64;
    const int warpN = (wid & 1) * 32;
    const int gm = blockIdx.x * 128;
    const int gn = blockIdx.y * 64;
    const int lt = lane & 3;
    const int lg = lane >> 2;

    float acc[4][4][4];
    #pragma unroll
    for (int mi = 0; mi < 4; mi++)
        #pragma unroll
        for (int nj = 0; nj < 4; nj++)
            #pragma unroll
            for (int r = 0; r < 4; r++) acc[mi][nj][r] = 0.f;

    const int nch = K >> 5;

    auto load_tiles = [&](int k0, int stage) {
        float* As = smem + stage * ASTG;
        float* Bs = smem + BOFF + stage * BSTG;
        #pragma unroll
        for (int i = 0; i < 8; i++) {
            int c  = tid + i * 128;
            int m  = c >> 3;
            int k4 = (c & 7) << 2;
            cp16(As + m * AK + k4, A + (size_t)(gm + m) * K + k0 + k4);
        }
        #pragma unroll
        for (int i = 0; i < 16; i++) {
            int c  = tid + i * 128;
            int kr = c >> 6;
            int n  = c & 63;
            int col = gn + n;
            cp4z(Bs + kr * BN2 + n, Bm + (size_t)(k0 + kr) * ldB + col,
                 (col < ldB) ? 4 : 0);
        }
    };

    load_tiles(0, 0);
    CP_COMMIT();

    for (int ch = 0; ch < nch; ch++) {
        int stage = ch & 1;
        if (ch + 1 < nch) load_tiles((ch + 1) << 5, stage ^ 1);
        CP_COMMIT();
        CP_WAIT1();
        __syncthreads();

        const float* Asb = smem + stage * ASTG;
        const float* Bsb = smem + BOFF + stage * BSTG;

        #pragma unroll
        for (int kk = 0; kk < 32; kk += 8) {
            unsigned a[4][4], b[4][2];
            #pragma unroll
            for (int mi = 0; mi < 4; mi++) {
                const float* p0 = Asb + (warpM + mi * 16 + lg) * AK + kk;
                const float* p1 = p0 + 8 * AK;
                a[mi][0] = __float_as_uint(p0[lt]);
                a[mi][1] = __float_as_uint(p1[lt]);
                a[mi][2] = __float_as_uint(p0[lt + 4]);
                a[mi][3] = __float_as_uint(p1[lt + 4]);
            }
            #pragma unroll
            for (int nj = 0; nj < 4; nj++) {
                int nc = warpN + nj * 8 + lg;
                b[nj][0] = f2tf(Bsb[(kk + lt) * BN2 + nc]);
                b[nj][1] = f2tf(Bsb[(kk + lt + 4) * BN2 + nc]);
            }
            #pragma unroll
            for (int mi = 0; mi < 4; mi++)
                #pragma unroll
                for (int nj = 0; nj < 4; nj++)
                    mma_tf32(acc[mi][nj], a[mi], b[nj]);
        }
        __syncthreads();
    }

    // epilogue: write C + per-(row, 32-col half) logsumexp partials
    const int halfIdx = (gn >> 5) + (warpN >> 5);
    #pragma unroll
    for (int mi = 0; mi < 4; mi++) {
        #pragma unroll
        for (int rh = 0; rh < 2; rh++) {
            int rowg = gm + warpM + mi * 16 + rh * 8 + lg;
            float vv[8];
            float rm = -FLT_MAX;
            #pragma unroll
            for (int nj = 0; nj < 4; nj++) {
                #pragma unroll
                for (int rl = 0; rl < 2; rl++) {
                    int colg = gn + warpN + nj * 8 + (lt << 1) + rl;
                    float v = -FLT_MAX;
                    if (colg < Ncols) {
                        v = acc[mi][nj][rh * 2 + rl] + bias[colg];
                        C[(size_t)rowg * Ncols + colg] = v;
                        rm = fmaxf(rm, v);
                    }
                    vv[nj * 2 + rl] = v;
                }
            }
            rm = fmaxf(rm, __shfl_xor_sync(0xffffffffu, rm, 1));
            rm = fmaxf(rm, __shfl_xor_sync(0xffffffffu, rm, 2));
            float rs = 0.f;
            #pragma unroll
            for (int j = 0; j < 8; j++)
                if (vv[j] > -FLT_MAX) rs += __expf(vv[j] - rm);
            rs += __shfl_xor_sync(0xffffffffu, rs, 1);
            rs += __shfl_xor_sync(0xffffffffu, rs, 2);
            if (lt == 0)
                part[(size_t)rowg * NHALF + halfIdx] = make_float2(rm, rs);
        }
    }
}

// ---------------- fused flash attention (tf32 mma, online softmax) ----------------
#define FQ 68
#define FK 72
#define FV 72
#define FP 68
#define OQ  0
#define OKK (64*FQ)
#define OVV (OKK + 64*FK)
#define OPP (OVV + 64*FV)
#define ORM (OPP + 64*FP)
#define ORS (ORM + 128)
#define FL_SMEM ((ORS + 128) * 4)   // 72704 bytes

__global__ __launch_bounds__(128)
void flash_attn(const float* __restrict__ qkv, float* __restrict__ o) {
    extern __shared__ float fsm[];
    float* Qs = fsm + OQ;
    float* Ks = fsm + OKK;
    float* Vs = fsm + OVV;
    float* Ps = fsm + OPP;
    float* Rm = fsm + ORM;
    float* Rs = fsm + ORS;

    const int tb = blockIdx.x, bh = blockIdx.y;
    const int b = bh / NH, h = bh % NH;
    const int tid = threadIdx.x;
    const int lane = tid & 31, wid = tid >> 5;
    const int warpM = (wid >> 1) * 32, warpN = (wid & 1) * 32;
    const int lt = lane & 3, lg = lane >> 2;
    const int nhalf = wid & 1;

    const float* qb = qkv + (size_t)b * TT * D3 + (size_t)h * HD;
    const float* kb = qb + D;
    const float* vb = qb + 2 * D;

    #pragma unroll
    for (int i = 0; i < 8; i++) {
        int c  = tid + i * 128;
        int m  = c >> 4;
        int d4 = (c & 15) << 2;
        *(float4*)(Qs + m * FQ + d4) =
            *(const float4*)(qb + (size_t)(tb * 64 + m) * D3 + d4);
    }

    float om[4], ol[4];
    float oacc[2][4][4];
    #pragma unroll
    for (int ri = 0; ri < 4; ri++) { om[ri] = -FLT_MAX; ol[ri] = 0.f; }
    #pragma unroll
    for (int mi = 0; mi < 2; mi++)
        #pragma unroll
        for (int nj = 0; nj < 4; nj++)
            #pragma unroll
            for (int r = 0; r < 4; r++) oacc[mi][nj][r] = 0.f;

    for (int sb = 0; sb <= tb; sb++) {
        __syncthreads();

        #pragma unroll
        for (int i = 0; i < 32; i++) {
            int c = tid + i * 128;
            int s = c >> 6;
            int d = c & 63;
            Ks[d * FK + s] = kb[(size_t)(sb * 64 + s) * D3 + d];
        }
        #pragma unroll
        for (int i = 0; i < 8; i++) {
            int c  = tid + i * 128;
            int m  = c >> 4;
            int d4 = (c & 15) << 2;
            *(float4*)(Vs + m * FV + d4) =
                *(const float4*)(vb + (size_t)(sb * 64 + m) * D3 + d4);
        }
        __syncthreads();

        float sacc[2][4][4];
        #pragma unroll
        for (int mi = 0; mi < 2; mi++)
            #pragma unroll
            for (int nj = 0; nj < 4; nj++)
                #pragma unroll
                for (int r = 0; r < 4; r++) sacc[mi][nj][r] = 0.f;

        #pragma unroll
        for (int kk = 0; kk < 64; kk += 8) {
            unsigned afr[2][4], bfr[4][2];
            #pragma unroll
            for (int mi = 0; mi < 2; mi++) {
                const float* p0 = Qs + (warpM + mi * 16 + lg) * FQ + kk;
                const float* p1 = p0 + 8 * FQ;
                afr[mi][0] = f2tf(p0[lt]);
                afr[mi][1] = f2tf(p1[lt]);
                afr[mi][2] = f2tf(p0[lt + 4]);
                afr[mi][3] = f2tf(p1[lt + 4]);
            }
            #pragma unroll
            for (int nj = 0; nj < 4; nj++) {
                int nc = warpN + nj * 8 + lg;
                bfr[nj][0] = f2tf(Ks[(kk + lt) * FK + nc]);
                bfr[nj][1] = f2tf(Ks[(kk + lt + 4) * FK + nc]);
            }
            #pragma unroll
            for (int mi = 0; mi < 2; mi++)
                #pragma unroll
                for (int nj = 0; nj < 4; nj++)
                    mma_tf32(sacc[mi][nj], afr[mi], bfr[nj]);
        }

        float rmax[4] = {-FLT_MAX, -FLT_MAX, -FLT_MAX, -FLT_MAX};
        #pragma unroll
        for (int mi = 0; mi < 2; mi++)
            #pragma unroll
            for (int nj = 0; nj < 4; nj++)
                #pragma unroll
                for (int r = 0; r < 4; r++) {
                    int tl = warpM + mi * 16 + lg + ((r >> 1) << 3);
                    int sl = warpN + nj * 8 + (lt << 1) + (r & 1);
                    float sv = sacc[mi][nj][r] * SCALE;
                    if (sb == tb && sl > tl) sv = -1e30f;
                    sacc[mi][nj][r] = sv;
                    int ri = mi * 2 + (r >> 1);
                    rmax[ri] = fmaxf(rmax[ri], sv);
                }
        #pragma unroll
        for (int ri = 0; ri < 4; ri++) {
            rmax[ri] = fmaxf(rmax[ri], __shfl_xor_sync(0xffffffffu, rmax[ri], 1));
            rmax[ri] = fmaxf(rmax[ri], __shfl_xor_sync(0xffffffffu, rmax[ri], 2));
        }
        if (lt == 0) {
            #pragma unroll
            for (int mi = 0; mi < 2; mi++)
                #pragma unroll
                for (int rh = 0; rh < 2; rh++)
                    Rm[nhalf * 64 + warpM + mi * 16 + rh * 8 + lg] = rmax[mi * 2 + rh];
        }
        __syncthreads();

        float mnew[4], cfac[4];
        #pragma unroll
        for (int mi = 0; mi < 2; mi++)
            #pragma unroll
            for (int rh = 0; rh < 2; rh++) {
                int ri  = mi * 2 + rh;
                int row = warpM + mi * 16 + rh * 8 + lg;
                float mb = fmaxf(Rm[row], Rm[64 + row]);
                float mn = fmaxf(om[ri], mb);
                cfac[ri] = __expf(om[ri] - mn);
                mnew[ri] = mn;
            }

        float rsum[4] = {0.f, 0.f, 0.f, 0.f};
        #pragma unroll
        for (int mi = 0; mi < 2; mi++)
            #pragma unroll
            for (int nj = 0; nj < 4; nj++)
                #pragma unroll
                for (int r = 0; r < 4; r++) {
                    int ri = mi * 2 + (r >> 1);
                    float pv = __expf(sacc[mi][nj][r] - mnew[ri]);
                    int tl = warpM + mi * 16 + lg + ((r >> 1) << 3);
                    int sl = warpN + nj * 8 + (lt << 1) + (r & 1);
                    Ps[tl * FP + sl] = pv;
                    rsum[ri] += pv;
                    oacc[mi][nj][r] *= cfac[ri];
                }
        #pragma unroll
        for (int ri = 0; ri < 4; ri++) {
            rsum[ri] += __shfl_xor_sync(0xffffffffu, rsum[ri], 1);
            rsum[ri] += __shfl_xor_sync(0xffffffffu, rsum[ri], 2);
            om[ri] = mnew[ri];
        }
        if (lt == 0) {
            #pragma unroll
            for (int mi = 0; mi < 2; mi++)
                #pragma unroll
                for (int rh = 0; rh < 2; rh++)
                    Rs[nhalf * 64 + warpM + mi * 16 + rh * 8 + lg] = rsum[mi * 2 + rh];
        }
        __syncthreads();
        #pragma unroll
        for (int mi = 0; mi < 2; mi++)
            #pragma unroll
            for (int rh = 0; rh < 2; rh++) {
                int ri  = mi * 2 + rh;
                int row = warpM + mi * 16 + rh * 8 + lg;
                ol[ri] = ol[ri] * cfac[ri] + Rs[row] + Rs[64 + row];
            }

        #pragma unroll
        for (int kk = 0; kk < 64; kk += 8) {
            unsigned afr[2][4], bfr[4][2];
            #pragma unroll
            for (int mi = 0; mi < 2; mi++) {
                const float* p0 = Ps + (warpM + mi * 16 + lg) * FP + kk;
                const float* p1 = p0 + 8 * FP;
                afr[mi][0] = f2tf(p0[lt]);
                afr[mi][1] = f2tf(p1[lt]);
                afr[mi][2] = f2tf(p0[lt + 4]);
                afr[mi][3] = f2tf(p1[lt + 4]);
            }
            #pragma unroll
            for (int nj = 0; nj < 4; nj++) {
                int nc = warpN + nj * 8 + lg;
                bfr[nj][0] = f2tf(Vs[(kk + lt) * FV + nc]);
                bfr[nj][1] = f2tf(Vs[(kk + lt + 4) * FV + nc]);
            }
            #pragma unroll
            for (int mi = 0; mi < 2; mi++)
                #pragma unroll
                for (int nj = 0; nj < 4; nj++)
                    mma_tf32(oacc[mi][nj], afr[mi], bfr[nj]);
        }
    }

    float* ob = o + (size_t)(b * TT + tb * 64) * D + (size_t)h * HD;
    #pragma unroll
    for (int mi = 0; mi < 2; mi++)
        #pragma unroll
        for (int nj = 0; nj < 4; nj++)
            #pragma unroll
            for (int r = 0; r < 4; r++) {
                int ri = mi * 2 + (r >> 1);
                int tl = warpM + mi * 16 + lg + ((r >> 1) << 3);
                int dl = warpN + nj * 8 + (lt << 1) + (r & 1);
                ob[(size_t)tl * D + dl] = tf32f(oacc[mi][nj][r] / ol[ri]);
            }
}

// ---------------- NLL from logsumexp partials ----------------
__global__ void nll_reduce(const float2* __restrict__ part,
                           const float* __restrict__ logits,
                           const int* __restrict__ targets,
                           float* __restrict__ nll) {
    int row = blockIdx.x;
    const float2* pr = part + (size_t)row * NHALF;
    int tid = threadIdx.x;

    float m = -FLT_MAX, s = 0.f;
    for (int i = tid; i < NHALF; i += 256) {
        float2 p = pr[i];
        float M = fmaxf(m, p.x);
        s = s * __expf(m - M) + p.y * __expf(p.x - M);
        m = M;
    }
    __shared__ float sm[256], ss[256];
    sm[tid] = m; ss[tid] = s; __syncthreads();
    #pragma unroll
    for (int off = 128; off > 0; off >>= 1) {
        if (tid < off) {
            float m2 = sm[tid + off], s2 = ss[tid + off];
            float M = fmaxf(sm[tid], m2);
            ss[tid] = ss[tid] * __expf(sm[tid] - M) + s2 * __expf(m2 - M);
            sm[tid] = M;
        }
        __syncthreads();
    }
    if (tid == 0)
        nll[row] = sm[0] + logf(ss[0]) - logits[(size_t)row * VV + targets[row]];
}

__global__ void loss_kernel(const float* __restrict__ nll, float* __restrict__ dst,
                            int nextra) {
    __shared__ float red[256];
    int tid = threadIdx.x;
    float s = 0.f;
    for (int i = tid; i < BT; i += 256) s += nll[i];
    red[tid] = s; __syncthreads();
    #pragma unroll
    for (int off = 128; off > 0; off >>= 1) {
        if (tid < off) red[tid] += red[tid + off];
        __syncthreads();
    }
    if (tid == 0) {
        float loss = red[0] * (1.f / BT);
        for (int i = 0; i < nextra; i++) dst[i] = loss;
    }
}

// ---------------- launch ----------------
extern "C" void kernel_launch(void* const* d_in, const int* in_sizes, int n_in,
                              void* d_out, int out_size) {
    const int*   idx     = (const int*)  d_in[0];
    const int*   targets = (const int*)  d_in[1];
    const float* tok_emb = (const float*)d_in[2];
    const float* pos_emb = (const float*)d_in[3];
    const float* Wq      = (const float*)d_in[4];
    const float* Wk      = (const float*)d_in[5];
    const float* Wv      = (const float*)d_in[6];
    const float* Wo      = (const float*)d_in[7];
    const float* bo      = (const float*)d_in[8];
    const float* ln1_g   = (const float*)d_in[9];
    const float* ln1_b   = (const float*)d_in[10];
    const float* ln2_g   = (const float*)d_in[11];
    const float* ln2_b   = (const float*)d_in[12];
    const float* W1      = (const float*)d_in[13];
    const float* b1      = (const float*)d_in[14];
    const float* W2      = (const float*)d_in[15];
    const float* b2      = (const float*)d_in[16];
    const float* Wlm     = (const float*)d_in[17];
    const float* blm     = (const float*)d_in[18];

    float *x, *h, *qkv, *o, *ff, *wqkv, *nll;
    float2* part;
    cudaGetSymbolAddress((void**)&x,    g_x);
    cudaGetSymbolAddress((void**)&h,    g_h);
    cudaGetSymbolAddress((void**)&qkv,  g_qkv);
    cudaGetSymbolAddress((void**)&o,    g_o);
    cudaGetSymbolAddress((void**)&ff,   g_ff);
    cudaGetSymbolAddress((void**)&wqkv, g_wqkv);
    cudaGetSymbolAddress((void**)&part, g_part);
    cudaGetSymbolAddress((void**)&nll,  g_nll);

    cudaFuncSetAttribute(gemm_tf32,  cudaFuncAttributeMaxDynamicSharedMemorySize, GSMEM);
    cudaFuncSetAttribute(gemm_lm,    cudaFuncAttributeMaxDynamicSharedMemorySize, GSMEM);
    cudaFuncSetAttribute(flash_attn, cudaFuncAttributeMaxDynamicSharedMemorySize, FL_SMEM);

    pack_qkv_kernel<<<2048, 256>>>(Wq, Wk, Wv, wqkv);
    embed_kernel<<<(BT * D + 255) / 256, 256>>>(idx, tok_emb, pos_emb, x);

    dim3 gD(BT / 128, D / 64);               // 32 x 12
    dim3 gQKV(BT / 128, D3 / 64);            // 32 x 36
    dim3 gF(BT / 128, FF / 64);              // 32 x 48
    dim3 gV(BT / 128, (VV + 63) / 64);       // 32 x 786

    for (int l = 0; l < NL; l++) {
        const float* wqkv_l = wqkv + (size_t)l * D * D3;
        const float* wo = Wo + (size_t)l * D * D;
        const float* w1 = W1 + (size_t)l * D * FF;
        const float* w2 = W2 + (size_t)l * FF * D;
        int lastFF2 = (l == NL - 1) ? 1 : 0;   // round x for LM-head A operand

        ln_kernel<<<BT / 8, 256>>>(x, ln1_g + (size_t)l * D, ln1_b + (size_t)l * D, h);
        gemm_tf32<<<gQKV, 128, GSMEM>>>(h, wqkv_l, nullptr, nullptr, qkv,
                                        BT, D3, D, D3, D3, 0, 0);

        flash_attn<<<dim3(TT / 64, BH), 128, FL_SMEM>>>(qkv, o);

        gemm_tf32<<<gD, 128, GSMEM>>>(o, wo, bo + (size_t)l * D, x, x,
                                      BT, D, D, D, D, 0, 0);

        ln_kernel<<<BT / 8, 256>>>(x, ln2_g + (size_t)l * D, ln2_b + (size_t)l * D, h);
        gemm_tf32<<<gF, 128, GSMEM>>>(h, w1, b1 + (size_t)l * FF, nullptr, ff,
                                      BT, FF, D, FF, FF, 1, 1);
        gemm_tf32<<<gD, 128, GSMEM>>>(ff, w2, b2 + (size_t)l * D, x, x,
                                      BT, D, FF, D, D, 0, lastFF2);
    }

    float* logits = (float*)d_out;
    gemm_lm<<<gV, 128, GSMEM>>>(x, Wlm, blm, logits, VV, D, VV, part);

    long long btv = (long long)BT * VV;
    if ((long long)out_size > btv) {
        nll_reduce<<<BT, 256>>>(part, logits, targets, nll);
        loss_kernel<<<1, 256>>>(nll, logits + btv, (int)((long long)out_size - btv));
    }
}

// round 17
// speedup vs baseline: 1.3530x; 1.0060x over previous
#include <cuda_runtime.h>
#include <cuda_bf16.h>
#include <stdint.h>
#include <float.h>
#include <math.h>

// ---------------- problem constants ----------------
#define NL   12
#define D    768
#define NH   12
#define HD   64
#define VV   50257
#define BB   4
#define TT   1024
#define BT   (BB*TT)          // 4096
#define FF   (4*D)            // 3072
#define BH   (BB*NH)          // 48
#define D3   (3*D)            // 2304
#define NHALF 1572            // ceil(VV/64)*2 column-half partials per row
#define EPSF 1e-5f
#define SCALE 0.125f          // HD^-0.5

// ---------------- scratch (device globals; no runtime alloc) ----------------
__device__ float g_x[BT*D];
__device__ float g_h[BT*D];
__device__ float g_qkv[(size_t)BT*D3];        // 37.7 MB
__device__ float g_o[BT*D];
__device__ float g_ff[BT*FF];
__device__ float g_wqkv[(size_t)NL*D*D3];     // 84.9 MB
__device__ float2 g_part[(size_t)BT*NHALF];   // 51.5 MB logsumexp partials
__device__ float g_nll[BT];

// ---------------- tf32 / async helpers ----------------
__device__ __forceinline__ unsigned f2tf(float x) {
    unsigned r;
    asm("cvt.rna.tf32.f32 %0, %1;" : "=r"(r) : "f"(x));
    return r;
}
__device__ __forceinline__ float tf32f(float x) { return __uint_as_float(f2tf(x)); }

__device__ __forceinline__ void mma_tf32(float* d, const unsigned* a, const unsigned* b) {
    asm volatile(
        "mma.sync.aligned.m16n8k8.row.col.f32.tf32.tf32.f32 "
        "{%0,%1,%2,%3}, {%4,%5,%6,%7}, {%8,%9}, {%0,%1,%2,%3};"
        : "+f"(d[0]), "+f"(d[1]), "+f"(d[2]), "+f"(d[3])
        : "r"(a[0]), "r"(a[1]), "r"(a[2]), "r"(a[3]), "r"(b[0]), "r"(b[1]));
}
__device__ __forceinline__ void cp16(void* s, const void* g) {
    unsigned sa = (unsigned)__cvta_generic_to_shared(s);
    asm volatile("cp.async.cg.shared.global [%0], [%1], 16;" :: "r"(sa), "l"(g));
}
__device__ __forceinline__ void cp4z(void* s, const void* g, int srcbytes) {
    unsigned sa = (unsigned)__cvta_generic_to_shared(s);
    asm volatile("cp.async.ca.shared.global [%0], [%1], 4, %2;"
                 :: "r"(sa), "l"(g), "r"(srcbytes));
}
#define CP_COMMIT() asm volatile("cp.async.commit_group;")
#define CP_WAIT1()  asm volatile("cp.async.wait_group 1;")

// ---------------- QKV weight repack ----------------
__global__ void pack_qkv_kernel(const float* __restrict__ Wq,
                                const float* __restrict__ Wk,
                                const float* __restrict__ Wv,
                                float* __restrict__ out) {
    long long i = (long long)blockIdx.x * blockDim.x + threadIdx.x;
    long long stride = (long long)gridDim.x * blockDim.x;
    long long n = (long long)NL * D * D3;
    for (; i < n; i += stride) {
        long long lk = i / D3;
        int j = (int)(i - lk * D3);
        float v;
        if (j < D)        v = Wq[lk * D + j];
        else if (j < 2*D) v = Wk[lk * D + (j - D)];
        else              v = Wv[lk * D + (j - 2*D)];
        out[i] = v;
    }
}

// ---------------- embedding ----------------
__global__ void embed_kernel(const int* __restrict__ idx,
                             const float* __restrict__ tok,
                             const float* __restrict__ pos,
                             float* __restrict__ x) {
    int i = blockIdx.x * 256 + threadIdx.x;
    if (i >= BT * D) return;
    int row = i / D;
    int d   = i - row * D;
    int t   = row & (TT - 1);
    x[i] = tok[(size_t)idx[row] * D + d] + pos[(size_t)t * D + d];
}

// ---------------- layernorm: one warp per row, shuffle reductions ----------------
__global__ __launch_bounds__(256)
void ln_kernel(const float* __restrict__ x,
               const float* __restrict__ g,
               const float* __restrict__ b,
               float* __restrict__ out) {
    const int lane = threadIdx.x & 31;
    const int row  = blockIdx.x * 8 + (threadIdx.x >> 5);
    const float* xr = x + (size_t)row * D;

    float4 v[6];
    float s = 0.f;
    #pragma unroll
    for (int j = 0; j < 6; j++) {
        v[j] = *(const float4*)(xr + ((j * 32 + lane) << 2));
        s += (v[j].x + v[j].y) + (v[j].z + v[j].w);
    }
    #pragma unroll
    for (int off = 16; off > 0; off >>= 1)
        s += __shfl_xor_sync(0xffffffffu, s, off);
    float mean = s * (1.f / D);

    float s2 = 0.f;
    #pragma unroll
    for (int j = 0; j < 6; j++) {
        float d0 = v[j].x - mean, d1 = v[j].y - mean;
        float d2 = v[j].z - mean, d3 = v[j].w - mean;
        s2 += (d0 * d0 + d1 * d1) + (d2 * d2 + d3 * d3);
    }
    #pragma unroll
    for (int off = 16; off > 0; off >>= 1)
        s2 += __shfl_xor_sync(0xffffffffu, s2, off);
    float rstd = rsqrtf(s2 * (1.f / D) + EPSF);

    float* orow = out + (size_t)row * D;
    #pragma unroll
    for (int j = 0; j < 6; j++) {
        int base = (j * 32 + lane) << 2;
        float4 gv = *(const float4*)(g + base);
        float4 bv = *(const float4*)(b + base);
        float4 ov;
        ov.x = tf32f((v[j].x - mean) * rstd * gv.x + bv.x);
        ov.y = tf32f((v[j].y - mean) * rstd * gv.y + bv.y);
        ov.z = tf32f((v[j].z - mean) * rstd * gv.z + bv.z);
        ov.w = tf32f((v[j].w - mean) * rstd * gv.w + bv.w);
        *(float4*)(orow + base) = ov;
    }
}

// ---------------- TF32 GEMM, 128x64x32 block; single-buffer frags, 4 CTAs/SM ----------------
#define AK    36
#define BN2   72
#define ASTG  (128*AK)          // 4608
#define BSTG  (32*BN2)          // 2304
#define BOFF  (2*ASTG)
#define GSMEM ((2*ASTG + 2*BSTG) * 4)   // 55296 bytes

__global__ __launch_bounds__(128, 4)
void gemm_tf32(const float* __restrict__ A, const float* __restrict__ Bm,
               const float* __restrict__ bias, const float* __restrict__ resid,
               float* __restrict__ C, int M, int Ncols, int K, int ldB, int ldC,
               int relu, int roundC) {
    extern __shared__ float smem[];

    const int tid  = threadIdx.x;
    const int lane = tid & 31;
    const int wid  = tid >> 5;
    const int warpM = (wid >> 1) * 64;
    const int warpN = (wid & 1) * 32;
    const int gm = blockIdx.x * 128;
    const int gn = blockIdx.y * 64;
    const int lt = lane & 3;
    const int lg = lane >> 2;
    const bool alignedB = ((ldB & 3) == 0) && (gn + 64 <= ldB);

    float acc[4][4][4];
    #pragma unroll
    for (int mi = 0; mi < 4; mi++)
        #pragma unroll
        for (int nj = 0; nj < 4; nj++)
            #pragma unroll
            for (int r = 0; r < 4; r++) acc[mi][nj][r] = 0.f;

    const int nch = K >> 5;

    auto load_tiles = [&](int k0, int stage) {
        float* As = smem + stage * ASTG;
        float* Bs = smem + BOFF + stage * BSTG;
        #pragma unroll
        for (int i = 0; i < 8; i++) {
            int c  = tid + i * 128;
            int m  = c >> 3;
            int k4 = (c & 7) << 2;
            cp16(As + m * AK + k4, A + (size_t)(gm + m) * K + k0 + k4);
        }
        if (alignedB) {
            #pragma unroll
            for (int i = 0; i < 4; i++) {
                int c  = tid + i * 128;
                int kr = c >> 4;
                int n4 = (c & 15) << 2;
                cp16(Bs + kr * BN2 + n4, Bm + (size_t)(k0 + kr) * ldB + gn + n4);
            }
        } else {
            #pragma unroll
            for (int i = 0; i < 16; i++) {
                int c  = tid + i * 128;
                int kr = c >> 6;
                int n  = c & 63;
                int col = gn + n;
                cp4z(Bs + kr * BN2 + n, Bm + (size_t)(k0 + kr) * ldB + col,
                     (col < ldB) ? 4 : 0);
            }
        }
    };

    load_tiles(0, 0);
    CP_COMMIT();

    for (int ch = 0; ch < nch; ch++) {
        int stage = ch & 1;
        if (ch + 1 < nch) load_tiles((ch + 1) << 5, stage ^ 1);
        CP_COMMIT();
        CP_WAIT1();
        __syncthreads();

        const float* Asb = smem + stage * ASTG;
        const float* Bsb = smem + BOFF + stage * BSTG;

        #pragma unroll
        for (int kk = 0; kk < 32; kk += 8) {
            unsigned a[4][4], b[4][2];
            #pragma unroll
            for (int mi = 0; mi < 4; mi++) {
                const float* p0 = Asb + (warpM + mi * 16 + lg) * AK + kk;
                const float* p1 = p0 + 8 * AK;
                a[mi][0] = __float_as_uint(p0[lt]);
                a[mi][1] = __float_as_uint(p1[lt]);
                a[mi][2] = __float_as_uint(p0[lt + 4]);
                a[mi][3] = __float_as_uint(p1[lt + 4]);
            }
            #pragma unroll
            for (int nj = 0; nj < 4; nj++) {
                int nc = warpN + nj * 8 + lg;
                b[nj][0] = f2tf(Bsb[(kk + lt) * BN2 + nc]);
                b[nj][1] = f2tf(Bsb[(kk + lt + 4) * BN2 + nc]);
            }
            #pragma unroll
            for (int mi = 0; mi < 4; mi++)
                #pragma unroll
                for (int nj = 0; nj < 4; nj++)
                    mma_tf32(acc[mi][nj], a[mi], b[nj]);
        }
        __syncthreads();
    }

    #pragma unroll
    for (int mi = 0; mi < 4; mi++) {
        int r0 = gm + warpM + mi * 16 + lg;
        #pragma unroll
        for (int nj = 0; nj < 4; nj++) {
            int c0 = gn + warpN + nj * 8 + (lt << 1);
            #pragma unroll
            for (int r = 0; r < 4; r++) {
                int rowg = r0 + ((r >> 1) << 3);
                int colg = c0 + (r & 1);
                if (colg < Ncols) {
                    float v = acc[mi][nj][r];
                    if (bias)   v += bias[colg];
                    if (resid)  v += resid[(size_t)rowg * ldC + colg];
                    if (relu)   v = fmaxf(v, 0.f);
                    if (roundC) v = tf32f(v);
                    C[(size_t)rowg * ldC + colg] = v;
                }
            }
        }
    }
}

// ---------------- LM-head GEMM clone with fused logsumexp partials ----------------
__global__ __launch_bounds__(128, 4)
void gemm_lm(const float* __restrict__ A, const float* __restrict__ Bm,
             const float* __restrict__ bias, float* __restrict__ C,
             int Ncols, int K, int ldB, float2* __restrict__ part) {
    extern __shared__ float smem[];

    const int tid  = threadIdx.x;
    const int lane = tid & 31;
    const int wid  = tid >> 5;
    const int warpM = (wid >> 1) * 64;
    const int warpN = (wid & 1) * 32;
    const int gm = blockIdx.x * 128;
    const int gn = blockIdx.y * 64;
    const int lt = lane & 3;
    const int lg = lane >> 2;

    float acc[4][4][4];
    #pragma unroll
    for (int mi = 0; mi < 4; mi++)
        #pragma unroll
        for (int nj = 0; nj < 4; nj++)
            #pragma unroll
            for (int r = 0; r < 4; r++) acc[mi][nj][r] = 0.f;

    const int nch = K >> 5;

    auto load_tiles = [&](int k0, int stage) {
        float* As = smem + stage * ASTG;
        float* Bs = smem + BOFF + stage * BSTG;
        #pragma unroll
        for (int i = 0; i < 8; i++) {
            int c  = tid + i * 128;
            int m  = c >> 3;
            int k4 = (c & 7) << 2;
            cp16(As + m * AK + k4, A + (size_t)(gm + m) * K + k0 + k4);
        }
        #pragma unroll
        for (int i = 0; i < 16; i++) {
            int c  = tid + i * 128;
            int kr = c >> 6;
            int n  = c & 63;
            int col = gn + n;
            cp4z(Bs + kr * BN2 + n, Bm + (size_t)(k0 + kr) * ldB + col,
                 (col < ldB) ? 4 : 0);
        }
    };

    load_tiles(0, 0);
    CP_COMMIT();

    for (int ch = 0; ch < nch; ch++) {
        int stage = ch & 1;
        if (ch + 1 < nch) load_tiles((ch + 1) << 5, stage ^ 1);
        CP_COMMIT();
        CP_WAIT1();
        __syncthreads();

        const float* Asb = smem + stage * ASTG;
        const float* Bsb = smem + BOFF + stage * BSTG;

        #pragma unroll
        for (int kk = 0; kk < 32; kk += 8) {
            unsigned a[4][4], b[4][2];
            #pragma unroll
            for (int mi = 0; mi < 4; mi++) {
                const float* p0 = Asb + (warpM + mi * 16 + lg) * AK + kk;
                const float* p1 = p0 + 8 * AK;
                a[mi][0] = __float_as_uint(p0[lt]);
                a[mi][1] = __float_as_uint(p1[lt]);
                a[mi][2] = __float_as_uint(p0[lt + 4]);
                a[mi][3] = __float_as_uint(p1[lt + 4]);
            }
            #pragma unroll
            for (int nj = 0; nj < 4; nj++) {
                int nc = warpN + nj * 8 + lg;
                b[nj][0] = f2tf(Bsb[(kk + lt) * BN2 + nc]);
                b[nj][1] = f2tf(Bsb[(kk + lt + 4) * BN2 + nc]);
            }
            #pragma unroll
            for (int mi = 0; mi < 4; mi++)
                #pragma unroll
                for (int nj = 0; nj < 4; nj++)
                    mma_tf32(acc[mi][nj], a[mi], b[nj]);
        }
        __syncthreads();
    }

    const int halfIdx = (gn >> 5) + (warpN >> 5);
    #pragma unroll
    for (int mi = 0; mi < 4; mi++) {
        #pragma unroll
        for (int rh = 0; rh < 2; rh++) {
            int rowg = gm + warpM + mi * 16 + rh * 8 + lg;
            float vv[8];
            float rm = -FLT_MAX;
            #pragma unroll
            for (int nj = 0; nj < 4; nj++) {
                #pragma unroll
                for (int rl = 0; rl < 2; rl++) {
                    int colg = gn + warpN + nj * 8 + (lt << 1) + rl;
                    float v = -FLT_MAX;
                    if (colg < Ncols) {
                        v = acc[mi][nj][rh * 2 + rl] + bias[colg];
                        C[(size_t)rowg * Ncols + colg] = v;
                        rm = fmaxf(rm, v);
                    }
                    vv[nj * 2 + rl] = v;
                }
            }
            rm = fmaxf(rm, __shfl_xor_sync(0xffffffffu, rm, 1));
            rm = fmaxf(rm, __shfl_xor_sync(0xffffffffu, rm, 2));
            float rs = 0.f;
            #pragma unroll
            for (int j = 0; j < 8; j++)
                if (vv[j] > -FLT_MAX) rs += __expf(vv[j] - rm);
            rs += __shfl_xor_sync(0xffffffffu, rs, 1);
            rs += __shfl_xor_sync(0xffffffffu, rs, 2);
            if (lt == 0)
                part[(size_t)rowg * NHALF + halfIdx] = make_float2(rm, rs);
        }
    }
}

// ---------------- fused flash attention (tf32 mma, online softmax) ----------------
// Ps aliases Ks (safe: all Ks frag reads precede the Rm __syncthreads; Ps writes follow it).
#define FQ 68
#define FK 72
#define FV 72
#define FP 72
#define OQ  0
#define OKK (64*FQ)                 // 4352
#define OPP OKK                     // Ps aliases Ks (both 64*72 = 4608)
#define OVV (OKK + 64*FK)           // 8960
#define ORM (OVV + 64*FV)           // 13568
#define ORS (ORM + 128)             // 13696
#define FL_SMEM ((ORS + 128) * 4)   // 55296 bytes -> 4 CTAs/SM

__global__ __launch_bounds__(128)
void flash_attn(const float* __restrict__ qkv, float* __restrict__ o) {
    extern __shared__ float fsm[];
    float* Qs = fsm + OQ;
    float* Ks = fsm + OKK;
    float* Vs = fsm + OVV;
    float* Ps = fsm + OPP;
    float* Rm = fsm + ORM;
    float* Rs = fsm + ORS;

    const int tb = gridDim.x - 1 - blockIdx.x;   // long causal tiles first
    const int bh = blockIdx.y;
    const int b = bh / NH, h = bh % NH;
    const int tid = threadIdx.x;
    const int lane = tid & 31, wid = tid >> 5;
    const int warpM = (wid >> 1) * 32, warpN = (wid & 1) * 32;
    const int lt = lane & 3, lg = lane >> 2;
    const int nhalf = wid & 1;

    const float* qb = qkv + (size_t)b * TT * D3 + (size_t)h * HD;
    const float* kb = qb + D;
    const float* vb = qb + 2 * D;

    #pragma unroll
    for (int i = 0; i < 8; i++) {
        int c  = tid + i * 128;
        int m  = c >> 4;
        int d4 = (c & 15) << 2;
        *(float4*)(Qs + m * FQ + d4) =
            *(const float4*)(qb + (size_t)(tb * 64 + m) * D3 + d4);
    }

    float om[4], ol[4];
    float oacc[2][4][4];
    #pragma unroll
    for (int ri = 0; ri < 4; ri++) { om[ri] = -FLT_MAX; ol[ri] = 0.f; }
    #pragma unroll
    for (int mi = 0; mi < 2; mi++)
        #pragma unroll
        for (int nj = 0; nj < 4; nj++)
            #pragma unroll
            for (int r = 0; r < 4; r++) oacc[mi][nj][r] = 0.f;

    for (int sb = 0; sb <= tb; sb++) {
        __syncthreads();   // prior iter PV reads of Ps/Vs complete (Q load on first)

        #pragma unroll
        for (int i = 0; i < 32; i++) {
            int c = tid + i * 128;
            int s = c >> 6;
            int d = c & 63;
            Ks[d * FK + s] = kb[(size_t)(sb * 64 + s) * D3 + d];
        }
        #pragma unroll
        for (int i = 0; i < 8; i++) {
            int c  = tid + i * 128;
            int m  = c >> 4;
            int d4 = (c & 15) << 2;
            *(float4*)(Vs + m * FV + d4) =
                *(const float4*)(vb + (size_t)(sb * 64 + m) * D3 + d4);
        }
        __syncthreads();

        // ---- S = Q K^T (all Ks reads happen here, before the Rm sync) ----
        float sacc[2][4][4];
        #pragma unroll
        for (int mi = 0; mi < 2; mi++)
            #pragma unroll
            for (int nj = 0; nj < 4; nj++)
                #pragma unroll
                for (int r = 0; r < 4; r++) sacc[mi][nj][r] = 0.f;

        #pragma unroll
        for (int kk = 0; kk < 64; kk += 8) {
            unsigned afr[2][4], bfr[4][2];
            #pragma unroll
            for (int mi = 0; mi < 2; mi++) {
                const float* p0 = Qs + (warpM + mi * 16 + lg) * FQ + kk;
                const float* p1 = p0 + 8 * FQ;
                afr[mi][0] = f2tf(p0[lt]);
                afr[mi][1] = f2tf(p1[lt]);
                afr[mi][2] = f2tf(p0[lt + 4]);
                afr[mi][3] = f2tf(p1[lt + 4]);
            }
            #pragma unroll
            for (int nj = 0; nj < 4; nj++) {
                int nc = warpN + nj * 8 + lg;
                bfr[nj][0] = f2tf(Ks[(kk + lt) * FK + nc]);
                bfr[nj][1] = f2tf(Ks[(kk + lt + 4) * FK + nc]);
            }
            #pragma unroll
            for (int mi = 0; mi < 2; mi++)
                #pragma unroll
                for (int nj = 0; nj < 4; nj++)
                    mma_tf32(sacc[mi][nj], afr[mi], bfr[nj]);
        }

        float rmax[4] = {-FLT_MAX, -FLT_MAX, -FLT_MAX, -FLT_MAX};
        #pragma unroll
        for (int mi = 0; mi < 2; mi++)
            #pragma unroll
            for (int nj = 0; nj < 4; nj++)
                #pragma unroll
                for (int r = 0; r < 4; r++) {
                    int tl = warpM + mi * 16 + lg + ((r >> 1) << 3);
                    int sl = warpN + nj * 8 + (lt << 1) + (r & 1);
                    float sv = sacc[mi][nj][r] * SCALE;
                    if (sb == tb && sl > tl) sv = -1e30f;
                    sacc[mi][nj][r] = sv;
                    int ri = mi * 2 + (r >> 1);
                    rmax[ri] = fmaxf(rmax[ri], sv);
                }
        #pragma unroll
        for (int ri = 0; ri < 4; ri++) {
            rmax[ri] = fmaxf(rmax[ri], __shfl_xor_sync(0xffffffffu, rmax[ri], 1));
            rmax[ri] = fmaxf(rmax[ri], __shfl_xor_sync(0xffffffffu, rmax[ri], 2));
        }
        if (lt == 0) {
            #pragma unroll
            for (int mi = 0; mi < 2; mi++)
                #pragma unroll
                for (int rh = 0; rh < 2; rh++)
                    Rm[nhalf * 64 + warpM + mi * 16 + rh * 8 + lg] = rmax[mi * 2 + rh];
        }
        __syncthreads();   // after this: no warp reads Ks again; Ps writes are safe

        float mnew[4], cfac[4];
        #pragma unroll
        for (int mi = 0; mi < 2; mi++)
            #pragma unroll
            for (int rh = 0; rh < 2; rh++) {
                int ri  = mi * 2 + rh;
                int row = warpM + mi * 16 + rh * 8 + lg;
                float mb = fmaxf(Rm[row], Rm[64 + row]);
                float mn = fmaxf(om[ri], mb);
                cfac[ri] = __expf(om[ri] - mn);
                mnew[ri] = mn;
            }

        float rsum[4] = {0.f, 0.f, 0.f, 0.f};
        #pragma unroll
        for (int mi = 0; mi < 2; mi++)
            #pragma unroll
            for (int nj = 0; nj < 4; nj++)
                #pragma unroll
                for (int r = 0; r < 4; r++) {
                    int ri = mi * 2 + (r >> 1);
                    float pv = __expf(sacc[mi][nj][r] - mnew[ri]);
                    int tl = warpM + mi * 16 + lg + ((r >> 1) << 3);
                    int sl = warpN + nj * 8 + (lt << 1) + (r & 1);
                    Ps[tl * FP + sl] = pv;
                    rsum[ri] += pv;
                    oacc[mi][nj][r] *= cfac[ri];
                }
        #pragma unroll
        for (int ri = 0; ri < 4; ri++) {
            rsum[ri] += __shfl_xor_sync(0xffffffffu, rsum[ri], 1);
            rsum[ri] += __shfl_xor_sync(0xffffffffu, rsum[ri], 2);
            om[ri] = mnew[ri];
        }
        if (lt == 0) {
            #pragma unroll
            for (int mi = 0; mi < 2; mi++)
                #pragma unroll
                for (int rh = 0; rh < 2; rh++)
                    Rs[nhalf * 64 + warpM + mi * 16 + rh * 8 + lg] = rsum[mi * 2 + rh];
        }
        __syncthreads();
        #pragma unroll
        for (int mi = 0; mi < 2; mi++)
            #pragma unroll
            for (int rh = 0; rh < 2; rh++) {
                int ri  = mi * 2 + rh;
                int row = warpM + mi * 16 + rh * 8 + lg;
                ol[ri] = ol[ri] * cfac[ri] + Rs[row] + Rs[64 + row];
            }

        // ---- O += P @ V ----
        #pragma unroll
        for (int kk = 0; kk < 64; kk += 8) {
            unsigned afr[2][4], bfr[4][2];
            #pragma unroll
            for (int mi = 0; mi < 2; mi++) {
                const float* p0 = Ps + (warpM + mi * 16 + lg) * FP + kk;
                const float* p1 = p0 + 8 * FP;
                afr[mi][0] = f2tf(p0[lt]);
                afr[mi][1] = f2tf(p1[lt]);
                afr[mi][2] = f2tf(p0[lt + 4]);
                afr[mi][3] = f2tf(p1[lt + 4]);
            }
            #pragma unroll
            for (int nj = 0; nj < 4; nj++) {
                int nc = warpN + nj * 8 + lg;
                bfr[nj][0] = f2tf(Vs[(kk + lt) * FV + nc]);
                bfr[nj][1] = f2tf(Vs[(kk + lt + 4) * FV + nc]);
            }
            #pragma unroll
            for (int mi = 0; mi < 2; mi++)
                #pragma unroll
                for (int nj = 0; nj < 4; nj++)
                    mma_tf32(oacc[mi][nj], afr[mi], bfr[nj]);
        }
    }

    float* ob = o + (size_t)(b * TT + tb * 64) * D + (size_t)h * HD;
    #pragma unroll
    for (int mi = 0; mi < 2; mi++)
        #pragma unroll
        for (int nj = 0; nj < 4; nj++)
            #pragma unroll
            for (int r = 0; r < 4; r++) {
                int ri = mi * 2 + (r >> 1);
                int tl = warpM + mi * 16 + lg + ((r >> 1) << 3);
                int dl = warpN + nj * 8 + (lt << 1) + (r & 1);
                ob[(size_t)tl * D + dl] = tf32f(oacc[mi][nj][r] / ol[ri]);
            }
}

// ---------------- NLL from logsumexp partials ----------------
__global__ void nll_reduce(const float2* __restrict__ part,
                           const float* __restrict__ logits,
                           const int* __restrict__ targets,
                           float* __restrict__ nll) {
    int row = blockIdx.x;
    const float2* pr = part + (size_t)row * NHALF;
    int tid = threadIdx.x;

    float m = -FLT_MAX, s = 0.f;
    for (int i = tid; i < NHALF; i += 256) {
        float2 p = pr[i];
        float M = fmaxf(m, p.x);
        s = s * __expf(m - M) + p.y * __expf(p.x - M);
        m = M;
    }
    __shared__ float sm[256], ss[256];
    sm[tid] = m; ss[tid] = s; __syncthreads();
    #pragma unroll
    for (int off = 128; off > 0; off >>= 1) {
        if (tid < off) {
            float m2 = sm[tid + off], s2 = ss[tid + off];
            float M = fmaxf(sm[tid], m2);
            ss[tid] = ss[tid] * __expf(sm[tid] - M) + s2 * __expf(m2 - M);
            sm[tid] = M;
        }
        __syncthreads();
    }
    if (tid == 0)
        nll[row] = sm[0] + logf(ss[0]) - logits[(size_t)row * VV + targets[row]];
}

__global__ void loss_kernel(const float* __restrict__ nll, float* __restrict__ dst,
                            int nextra) {
    __shared__ float red[256];
    int tid = threadIdx.x;
    float s = 0.f;
    for (int i = tid; i < BT; i += 256) s += nll[i];
    red[tid] = s; __syncthreads();
    #pragma unroll
    for (int off = 128; off > 0; off >>= 1) {
        if (tid < off) red[tid] += red[tid + off];
        __syncthreads();
    }
    if (tid == 0) {
        float loss = red[0] * (1.f / BT);
        for (int i = 0; i < nextra; i++) dst[i] = loss;
    }
}

// ---------------- launch ----------------
extern "C" void kernel_launch(void* const* d_in, const int* in_sizes, int n_in,
                              void* d_out, int out_size) {
    const int*   idx     = (const int*)  d_in[0];
    const int*   targets = (const int*)  d_in[1];
    const float* tok_emb = (const float*)d_in[2];
    const float* pos_emb = (const float*)d_in[3];
    const float* Wq      = (const float*)d_in[4];
    const float* Wk      = (const float*)d_in[5];
    const float* Wv      = (const float*)d_in[6];
    const float* Wo      = (const float*)d_in[7];
    const float* bo      = (const float*)d_in[8];
    const float* ln1_g   = (const float*)d_in[9];
    const float* ln1_b   = (const float*)d_in[10];
    const float* ln2_g   = (const float*)d_in[11];
    const float* ln2_b   = (const float*)d_in[12];
    const float* W1      = (const float*)d_in[13];
    const float* b1      = (const float*)d_in[14];
    const float* W2      = (const float*)d_in[15];
    const float* b2      = (const float*)d_in[16];
    const float* Wlm     = (const float*)d_in[17];
    const float* blm     = (const float*)d_in[18];

    float *x, *h, *qkv, *o, *ff, *wqkv, *nll;
    float2* part;
    cudaGetSymbolAddress((void**)&x,    g_x);
    cudaGetSymbolAddress((void**)&h,    g_h);
    cudaGetSymbolAddress((void**)&qkv,  g_qkv);
    cudaGetSymbolAddress((void**)&o,    g_o);
    cudaGetSymbolAddress((void**)&ff,   g_ff);
    cudaGetSymbolAddress((void**)&wqkv, g_wqkv);
    cudaGetSymbolAddress((void**)&part, g_part);
    cudaGetSymbolAddress((void**)&nll,  g_nll);

    cudaFuncSetAttribute(gemm_tf32,  cudaFuncAttributeMaxDynamicSharedMemorySize, GSMEM);
    cudaFuncSetAttribute(gemm_lm,    cudaFuncAttributeMaxDynamicSharedMemorySize, GSMEM);
    cudaFuncSetAttribute(flash_attn, cudaFuncAttributeMaxDynamicSharedMemorySize, FL_SMEM);

    pack_qkv_kernel<<<2048, 256>>>(Wq, Wk, Wv, wqkv);
    embed_kernel<<<(BT * D + 255) / 256, 256>>>(idx, tok_emb, pos_emb, x);

    dim3 gD(BT / 128, D / 64);               // 32 x 12
    dim3 gQKV(BT / 128, D3 / 64);            // 32 x 36
    dim3 gF(BT / 128, FF / 64);              // 32 x 48
    dim3 gV(BT / 128, (VV + 63) / 64);       // 32 x 786

    for (int l = 0; l < NL; l++) {
        const float* wqkv_l = wqkv + (size_t)l * D * D3;
        const float* wo = Wo + (size_t)l * D * D;
        const float* w1 = W1 + (size_t)l * D * FF;
        const float* w2 = W2 + (size_t)l * FF * D;
        int lastFF2 = (l == NL - 1) ? 1 : 0;   // round x for LM-head A operand

        ln_kernel<<<BT / 8, 256>>>(x, ln1_g + (size_t)l * D, ln1_b + (size_t)l * D, h);
        gemm_tf32<<<gQKV, 128, GSMEM>>>(h, wqkv_l, nullptr, nullptr, qkv,
                                        BT, D3, D, D3, D3, 0, 0);

        flash_attn<<<dim3(TT / 64, BH), 128, FL_SMEM>>>(qkv, o);

        gemm_tf32<<<gD, 128, GSMEM>>>(o, wo, bo + (size_t)l * D, x, x,
                                      BT, D, D, D, D, 0, 0);

        ln_kernel<<<BT / 8, 256>>>(x, ln2_g + (size_t)l * D, ln2_b + (size_t)l * D, h);
        gemm_tf32<<<gF, 128, GSMEM>>>(h, w1, b1 + (size_t)l * FF, nullptr, ff,
                                      BT, FF, D, FF, FF, 1, 1);
        gemm_tf32<<<gD, 128, GSMEM>>>(ff, w2, b2 + (size_t)l * D, x, x,
                                      BT, D, FF, D, D, 0, lastFF2);
    }

    float* logits = (float*)d_out;
    gemm_lm<<<gV, 128, GSMEM>>>(x, Wlm, blm, logits, VV, D, VV, part);

    long long btv = (long long)BT * VV;
    if ((long long)out_size > btv) {
        nll_reduce<<<BT, 256>>>(part, logits, targets, nll);
        loss_kernel<<<1, 256>>>(nll, logits + btv, (int)((long long)out_size - btv));
    }
}